// round 1
// baseline (speedup 1.0000x reference)
#include <cuda_runtime.h>
#include <math.h>
#include <stdint.h>

// Problem constants
#define NROWS 8192
#define DIMK  512
#define CCLS  1000
#define LDPRED 1024
#define WPR   32           // 32 u32 words cover 1000 class bits
#define JCHUNKS 8          // big kernel: split the 64 j-tiles into 8 chunks

// ---------------- device scratch (static; no allocations allowed) ------------
__device__ float    g_feat[NROWS * DIMK];        // 16 MB  normalized features
__device__ float    g_proxy[CCLS * DIMK];        // 2 MB   projected+normalized proxies
__device__ float    g_pred[NROWS * LDPRED];      // 32 MB  feat @ proxy.T (ld=1024)
__device__ unsigned g_bits[NROWS * WPR];         // 1 MB   packed pred_class bits
__device__ unsigned g_summ[NROWS];               // bloom: bit w set iff word w != 0
__device__ float    g_pos[NROWS];                // pos_pair per row
__device__ int      g_candcnt[NROWS];            // candidates count (0 if conf)
__device__ int      g_notconf[NROWS];            // 1 if not confident
__device__ float    g_partial[JCHUNKS * NROWS];  // per-chunk sum of exp(valid sims)

// ---------------- row L2-normalize (D=512, 128 thr, float4) ------------------
__global__ void norm_rows_kernel(const float* __restrict__ in, float* __restrict__ out)
{
    __shared__ float wsum[4];
    int i = blockIdx.x;
    int t = threadIdx.x;
    float4 v = *(const float4*)&in[(size_t)i * DIMK + t * 4];
    float ss = v.x * v.x + v.y * v.y + v.z * v.z + v.w * v.w;
#pragma unroll
    for (int o = 16; o; o >>= 1) ss += __shfl_xor_sync(0xFFFFFFFFu, ss, o);
    if ((t & 31) == 0) wsum[t >> 5] = ss;
    __syncthreads();
    ss = wsum[0] + wsum[1] + wsum[2] + wsum[3];
    float inv = 1.0f / fmaxf(sqrtf(ss), 1e-12f);
    v.x *= inv; v.y *= inv; v.z *= inv; v.w *= inv;
    *(float4*)&out[(size_t)i * DIMK + t * 4] = v;
}

// ---------------- generic guarded NT SGEMM: C(M,N) = A(M,K) * B(N,K)^T -------
// 128x128 block tile, 16-deep K chunks, 256 threads, 8x8 microtile.
__global__ __launch_bounds__(256, 2)
void sgemm_nt_kernel(const float* __restrict__ A, const float* __restrict__ B,
                     float* __restrict__ C, int M, int N, int K, int ldc)
{
    __shared__ float As[16][128];
    __shared__ float Bs[16][128];
    int tid = threadIdx.x;
    int tr = tid >> 4, tc = tid & 15;
    int row0 = blockIdx.y * 128;
    int col0 = blockIdx.x * 128;
    int ldrow = tid >> 2;
    int ldk   = (tid & 3) * 4;

    float acc[8][8];
#pragma unroll
    for (int x = 0; x < 8; x++)
#pragma unroll
        for (int y = 0; y < 8; y++) acc[x][y] = 0.0f;

    for (int k0 = 0; k0 < K; k0 += 16) {
        __syncthreads();
#pragma unroll
        for (int h = 0; h < 2; h++) {
            int r = ldrow + 64 * h;
            float4 va = make_float4(0.f, 0.f, 0.f, 0.f);
            float4 vb = make_float4(0.f, 0.f, 0.f, 0.f);
            if (row0 + r < M) va = *(const float4*)&A[(size_t)(row0 + r) * K + k0 + ldk];
            if (col0 + r < N) vb = *(const float4*)&B[(size_t)(col0 + r) * K + k0 + ldk];
            As[ldk + 0][r] = va.x; As[ldk + 1][r] = va.y;
            As[ldk + 2][r] = va.z; As[ldk + 3][r] = va.w;
            Bs[ldk + 0][r] = vb.x; Bs[ldk + 1][r] = vb.y;
            Bs[ldk + 2][r] = vb.z; Bs[ldk + 3][r] = vb.w;
        }
        __syncthreads();
#pragma unroll
        for (int kk = 0; kk < 16; kk++) {
            float a[8], b[8];
            *(float4*)&a[0] = *(const float4*)&As[kk][tr * 8];
            *(float4*)&a[4] = *(const float4*)&As[kk][tr * 8 + 4];
            *(float4*)&b[0] = *(const float4*)&Bs[kk][tc * 8];
            *(float4*)&b[4] = *(const float4*)&Bs[kk][tc * 8 + 4];
#pragma unroll
            for (int x = 0; x < 8; x++)
#pragma unroll
                for (int y = 0; y < 8; y++) acc[x][y] = fmaf(a[x], b[y], acc[x][y]);
        }
    }
#pragma unroll
    for (int x = 0; x < 8; x++) {
        int r = row0 + tr * 8 + x;
        if (r < M) {
#pragma unroll
            for (int y = 0; y < 8; y++) {
                int cc = col0 + tc * 8 + y;
                if (cc < N) C[(size_t)r * ldc + cc] = acc[x][y];
            }
        }
    }
}

// ---------------- per-row prob processing -------------------------------------
// top1 (first-occurrence argmax), candidate bits, sc_sim, pos_pair, counts.
__global__ void row_prob_kernel(const float* __restrict__ prob, const int* __restrict__ conf)
{
    __shared__ unsigned wbits[WPR];
    __shared__ float sval[256];
    __shared__ int   sidx[256];
    __shared__ float ssc[256];
    __shared__ int   scnt[256];

    int i = blockIdx.x;
    int t = threadIdx.x;
    bool conf_i = conf[i] != 0;

    if (t < WPR) wbits[t] = 0u;
    __syncthreads();

    float best = -INFINITY; int bidx = 0x7FFFFFFF;
    float sc = 0.0f; int cnt = 0;
    for (int c = t; c < CCLS; c += 256) {
        float p = prob[(size_t)i * CCLS + c];
        if (p > best) { best = p; bidx = c; }  // ascending scan -> first occurrence kept
        if (p > 0.001f) {                      // LOW_THRE = 1/1000 as f32
            atomicOr(&wbits[c >> 5], 1u << (c & 31));
            cnt++;
            sc += p * g_pred[(size_t)i * LDPRED + c];
        }
    }
    sval[t] = best; sidx[t] = bidx; ssc[t] = sc; scnt[t] = cnt;
    __syncthreads();
    for (int s = 128; s; s >>= 1) {
        if (t < s) {
            float ov = sval[t + s]; int oi = sidx[t + s];
            if (ov > sval[t] || (ov == sval[t] && oi < sidx[t])) { sval[t] = ov; sidx[t] = oi; }
            ssc[t] += ssc[t + s];
            scnt[t] += scnt[t + s];
        }
        __syncthreads();
    }
    if (t == 0) {
        int t1 = sidx[0];
        unsigned sm = 0;
#pragma unroll
        for (int w = 0; w < WPR; w++) {
            unsigned word = conf_i ? (((t1 >> 5) == w) ? (1u << (t1 & 31)) : 0u) : wbits[w];
            g_bits[(size_t)i * WPR + w] = word;
            if (word) sm |= 1u << w;
        }
        g_summ[i] = sm;
        g_pos[i] = conf_i ? g_pred[(size_t)i * LDPRED + t1] : ssc[0];
        g_candcnt[i] = conf_i ? 0 : scnt[0];
        g_notconf[i] = conf_i ? 0 : 1;
    }
}

// ---------------- fused NxN sim GEMM + mask + sum(exp) ------------------------
// grid: (JCHUNKS, 64). Each block: 128 rows x 1024 cols (8 j-tiles of 128).
// dynamic smem layout: As(8K) Bs(8K) rb(16K) cb(16K) csum(0.5K); red reuses As.
#define FUSED_SMEM (8192 + 8192 + 16384 + 16384 + 512)
__global__ __launch_bounds__(256, 2)
void fused_sim_kernel()
{
    extern __shared__ char smem[];
    float    (*As)[128] = (float(*)[128])(smem);
    float    (*Bs)[128] = (float(*)[128])(smem + 8192);
    unsigned (*rb)[WPR] = (unsigned(*)[WPR])(smem + 16384);
    unsigned (*cb)[WPR] = (unsigned(*)[WPR])(smem + 32768);
    unsigned *csum      = (unsigned*)(smem + 49152);
    float    *red       = (float*)smem;   // reuse As/Bs after last compute

    int tid = threadIdx.x;
    int tr = tid >> 4, tc = tid & 15;
    int i0 = blockIdx.y * 128;
    int chunk = blockIdx.x;
    int ldrow = tid >> 2;
    int ldk   = (tid & 3) * 4;

    for (int idx = tid; idx < 128 * WPR; idx += 256)
        ((unsigned*)rb)[idx] = g_bits[(size_t)i0 * WPR + idx];

    unsigned rsum[8];
#pragma unroll
    for (int a = 0; a < 8; a++) rsum[a] = g_summ[i0 + tr * 8 + a];

    float srow[8] = {0.f, 0.f, 0.f, 0.f, 0.f, 0.f, 0.f, 0.f};

    for (int jt = 0; jt < 8; jt++) {
        int j0 = (chunk * 8 + jt) * 128;
        __syncthreads();   // previous epilogue done reading cb/csum
        for (int idx = tid; idx < 128 * WPR; idx += 256)
            ((unsigned*)cb)[idx] = g_bits[(size_t)j0 * WPR + idx];
        if (tid < 128) csum[tid] = g_summ[j0 + tid];

        float acc[8][8];
#pragma unroll
        for (int x = 0; x < 8; x++)
#pragma unroll
            for (int y = 0; y < 8; y++) acc[x][y] = 0.0f;

        for (int k0 = 0; k0 < DIMK; k0 += 16) {
            __syncthreads();
            float4 va0 = *(const float4*)&g_feat[(size_t)(i0 + ldrow)      * DIMK + k0 + ldk];
            float4 va1 = *(const float4*)&g_feat[(size_t)(i0 + ldrow + 64) * DIMK + k0 + ldk];
            float4 vb0 = *(const float4*)&g_feat[(size_t)(j0 + ldrow)      * DIMK + k0 + ldk];
            float4 vb1 = *(const float4*)&g_feat[(size_t)(j0 + ldrow + 64) * DIMK + k0 + ldk];
            As[ldk + 0][ldrow] = va0.x; As[ldk + 1][ldrow] = va0.y;
            As[ldk + 2][ldrow] = va0.z; As[ldk + 3][ldrow] = va0.w;
            As[ldk + 0][ldrow + 64] = va1.x; As[ldk + 1][ldrow + 64] = va1.y;
            As[ldk + 2][ldrow + 64] = va1.z; As[ldk + 3][ldrow + 64] = va1.w;
            Bs[ldk + 0][ldrow] = vb0.x; Bs[ldk + 1][ldrow] = vb0.y;
            Bs[ldk + 2][ldrow] = vb0.z; Bs[ldk + 3][ldrow] = vb0.w;
            Bs[ldk + 0][ldrow + 64] = vb1.x; Bs[ldk + 1][ldrow + 64] = vb1.y;
            Bs[ldk + 2][ldrow + 64] = vb1.z; Bs[ldk + 3][ldrow + 64] = vb1.w;
            __syncthreads();
#pragma unroll
            for (int kk = 0; kk < 16; kk++) {
                float a[8], b[8];
                *(float4*)&a[0] = *(const float4*)&As[kk][tr * 8];
                *(float4*)&a[4] = *(const float4*)&As[kk][tr * 8 + 4];
                *(float4*)&b[0] = *(const float4*)&Bs[kk][tc * 8];
                *(float4*)&b[4] = *(const float4*)&Bs[kk][tc * 8 + 4];
#pragma unroll
                for (int x = 0; x < 8; x++)
#pragma unroll
                    for (int y = 0; y < 8; y++) acc[x][y] = fmaf(a[x], b[y], acc[x][y]);
            }
        }

        // epilogue: masked sum of exp(sim)
        unsigned csm[8];
#pragma unroll
        for (int b = 0; b < 8; b++) csm[b] = csum[tc * 8 + b];
#pragma unroll
        for (int a = 0; a < 8; a++) {
            float se = 0.0f;
#pragma unroll
            for (int b = 0; b < 8; b++) {
                float v = acc[a][b];
                if (v >= 1e-6f) {                         // sim<1e-6 -> -inf -> exp 0
                    unsigned hit = rsum[a] & csm[b];      // bloom prefilter
                    bool masked = false;
                    while (hit) {
                        int w = __ffs((int)hit) - 1;
                        if (rb[tr * 8 + a][w] & cb[tc * 8 + b][w]) { masked = true; break; }
                        hit &= hit - 1;
                    }
                    if (!masked) se += __expf(v);
                }
            }
            srow[a] += se;
        }
    }

    // reduce srow across the 16 threads sharing each row
    __syncthreads();
#pragma unroll
    for (int a = 0; a < 8; a++) red[(tr * 8 + a) * 16 + tc] = srow[a];
    __syncthreads();
    if (tid < 128) {
        float s = 0.0f;
#pragma unroll
        for (int t = 0; t < 16; t++) s += red[tid * 16 + t];
        g_partial[(size_t)chunk * NROWS + i0 + tid] = s;
    }
}

// ---------------- final reduction: loss + sc_num ------------------------------
__global__ void final_kernel(float* __restrict__ out)
{
    __shared__ float sl[256];
    __shared__ int   sc[256];
    __shared__ int   sn[256];
    int t = threadIdx.x;
    float lacc = 0.0f; int cacc = 0, nacc = 0;
    for (int i = t; i < NROWS; i += 256) {
        float pos = g_pos[i];
        float S = expf(pos);
#pragma unroll
        for (int ch = 0; ch < JCHUNKS; ch++) S += g_partial[(size_t)ch * NROWS + i];
        lacc += logf(S) - pos;     // -logp0
        cacc += g_candcnt[i];
        nacc += g_notconf[i];
    }
    sl[t] = lacc; sc[t] = cacc; sn[t] = nacc;
    __syncthreads();
    for (int s = 128; s; s >>= 1) {
        if (t < s) { sl[t] += sl[t + s]; sc[t] += sc[t + s]; sn[t] += sn[t + s]; }
        __syncthreads();
    }
    if (t == 0) {
        out[0] = sl[0] / (float)NROWS;
        out[1] = (sn[0] > 0) ? ((float)sc[0] / (float)sn[0]) : 0.0f;
    }
}

// ---------------- launch --------------------------------------------------------
extern "C" void kernel_launch(void* const* d_in, const int* in_sizes, int n_in,
                              void* d_out, int out_size)
{
    const float* feature   = (const float*)d_in[0];   // (8192, 512)
    const float* proxy_raw = (const float*)d_in[1];   // (1000, 512)
    const float* cPw       = (const float*)d_in[2];   // (512, 512)
    const float* prob      = (const float*)d_in[3];   // (8192, 1000)
    const int*   conf      = (const int*)d_in[4];     // (8192,) bool as int32
    float* out = (float*)d_out;

    void *p_feat, *p_proxy, *p_pred;
    cudaGetSymbolAddress(&p_feat, g_feat);
    cudaGetSymbolAddress(&p_proxy, g_proxy);
    cudaGetSymbolAddress(&p_pred, g_pred);

    // 1) feat = l2norm(feature)
    norm_rows_kernel<<<NROWS, 128>>>(feature, (float*)p_feat);

    // 2) proxy_tmp = proxy_raw @ cP_weight^T  (M=1000, N=512, K=512)
    sgemm_nt_kernel<<<dim3(4, 8), 256>>>(proxy_raw, cPw, (float*)p_proxy,
                                         CCLS, DIMK, DIMK, DIMK);

    // 3) proxy = l2norm(proxy_tmp) in place
    norm_rows_kernel<<<CCLS, 128>>>((const float*)p_proxy, (float*)p_proxy);

    // 4) pred = feat @ proxy^T  (M=8192, N=1000, K=512, ld=1024)
    sgemm_nt_kernel<<<dim3(8, 64), 256>>>((const float*)p_feat, (const float*)p_proxy,
                                          (float*)p_pred, NROWS, CCLS, DIMK, LDPRED);

    // 5) per-row: top1/candidates/bits/sc_sim/pos_pair/counters
    row_prob_kernel<<<NROWS, 256>>>(prob, conf);

    // 6) fused NxN sim + mask + sum-exp partials
    cudaFuncSetAttribute(fused_sim_kernel, cudaFuncAttributeMaxDynamicSharedMemorySize,
                         FUSED_SMEM);
    fused_sim_kernel<<<dim3(JCHUNKS, NROWS / 128), 256, FUSED_SMEM>>>();

    // 7) loss + sc_num
    final_kernel<<<1, 256>>>(out);
}

// round 3
// speedup vs baseline: 1.0309x; 1.0309x over previous
#include <cuda_runtime.h>
#include <math.h>
#include <stdint.h>

// ---------------- problem constants ----------------
#define NROWS  8192
#define DIMK   512
#define CCLS   1000
#define LDPRED 1024
#define WPR    32
#define NPAD   1024

// ---------------- device scratch (static) ----------------
__device__ float    g_feat[NROWS * DIMK];        // tf32-rounded normalized features
__device__ float    g_proxy[NPAD * DIMK];        // tf32-rounded normalized proxies (padded)
__device__ float    g_pred[NROWS * LDPRED];      // feat @ proxy^T
__device__ unsigned g_bits[NROWS * WPR];
__device__ unsigned g_summ[NROWS];
__device__ float    g_pos[NROWS];
__device__ int      g_candcnt[NROWS];
__device__ int      g_notconf[NROWS];
__device__ float    g_partial[64 * NROWS];       // per-jtile exp-sum partials

// ---------------- small helpers ----------------
__device__ __forceinline__ uint32_t smem_u32(const void* p) {
    uint32_t a;
    asm("{ .reg .u64 t; cvta.to.shared.u64 t, %1; cvt.u32.u64 %0, t; }" : "=r"(a) : "l"(p));
    return a;
}
__device__ __forceinline__ void sts_f(uint32_t a, float v) {
    asm volatile("st.shared.f32 [%0], %1;" :: "r"(a), "f"(v));
}
__device__ __forceinline__ float4 lds128(uint32_t a) {
    float4 r;
    asm volatile("ld.shared.v4.f32 {%0,%1,%2,%3}, [%4];"
                 : "=f"(r.x), "=f"(r.y), "=f"(r.z), "=f"(r.w) : "r"(a));
    return r;
}
__device__ __forceinline__ float tf32r(float x) {
    uint32_t u;
    asm("cvt.rna.tf32.f32 %0, %1;" : "=r"(u) : "f"(x));
    return __uint_as_float(u);
}
__device__ __forceinline__ void mma_tf32(float c[4], const uint32_t a[4], const uint32_t b[2]) {
    asm volatile(
        "mma.sync.aligned.m16n8k8.row.col.f32.tf32.tf32.f32 "
        "{%0,%1,%2,%3}, {%4,%5,%6,%7}, {%8,%9}, {%0,%1,%2,%3};"
        : "+f"(c[0]), "+f"(c[1]), "+f"(c[2]), "+f"(c[3])
        : "r"(a[0]), "r"(a[1]), "r"(a[2]), "r"(a[3]), "r"(b[0]), "r"(b[1]));
}

// ============== fragment-ordered smem GEMM core (128x128 tile, K-chunk 32) ====
// As layout: for kstep s(0..3), mtile m(0..7), lane l: float4 = (a0,a1,a2,a3)
//   a_j = A[m*16 + (l>>2) + 8*(j&1)][s*8 + (l&3) + 4*(j>>1)]   -> 16 KB
// Bs layout: for kstep s, pair p(0..7), lane l: float4 = (g=2p:b0,b1, g=2p+1:b0,b1)
//   b0 = B[p*16 + (j>=2)*8 + (l>>2)][s*8 + (l&3)], b1 same col, k+4  -> 16 KB

__device__ __forceinline__ void ldg_chunk(const float* __restrict__ Ar,
                                          const float* __restrict__ Br,
                                          int kc, int tid, float4* st)
{
    int koff = kc * 32;
#pragma unroll
    for (int ii = 0; ii < 4; ii++) {
        int q = tid + (ii << 8);
        int r = q >> 3, c4 = q & 7;
        st[ii]     = *(const float4*)(Ar + (size_t)r * DIMK + koff + (c4 << 2));
    }
#pragma unroll
    for (int ii = 0; ii < 4; ii++) {
        int q = tid + (ii << 8);
        int r = q >> 3, c4 = q & 7;
        st[4 + ii] = *(const float4*)(Br + (size_t)r * DIMK + koff + (c4 << 2));
    }
}

__device__ __forceinline__ void sts_chunk(uint32_t Ab, uint32_t Bb, int tid, const float4* st)
{
#pragma unroll
    for (int ii = 0; ii < 4; ii++) {
        int q = tid + (ii << 8);
        int r = q >> 3, c4 = q & 7;
        float v[4] = { st[ii].x, st[ii].y, st[ii].z, st[ii].w };
#pragma unroll
        for (int j = 0; j < 4; j++) {
            int k = (c4 << 2) + j, s = k >> 3, kk = k & 7, m = r >> 4, rr = r & 15;
            uint32_t lane = ((rr & 7) << 2) | (kk & 3);
            uint32_t reg  = (uint32_t)((rr >> 3) | ((kk >> 2) << 1));
            sts_f(Ab + (((((s << 3) | m) << 5) | lane) << 4) + (reg << 2), v[j]);
        }
    }
#pragma unroll
    for (int ii = 0; ii < 4; ii++) {
        int q = tid + (ii << 8);
        int r = q >> 3, c4 = q & 7;
        float v[4] = { st[4+ii].x, st[4+ii].y, st[4+ii].z, st[4+ii].w };
#pragma unroll
        for (int j = 0; j < 4; j++) {
            int k = (c4 << 2) + j, s = k >> 3, kk = k & 7, g = r >> 3, nl = r & 7;
            uint32_t lane = ((uint32_t)nl << 2) | (kk & 3);
            uint32_t slot = (uint32_t)(((g & 1) << 1) | (kk >> 2));
            uint32_t pair = (uint32_t)(g >> 1);
            sts_f(Bb + (((((s << 3) | pair) << 5) | lane) << 4) + (slot << 2), v[j]);
        }
    }
}

__device__ __forceinline__ void compute_chunk(uint32_t Ab, uint32_t Bb,
                                              float acc[4][4][4], int wr, int wc, int lane)
{
#pragma unroll
    for (int s = 0; s < 4; s++) {
        uint32_t a[4][4];
#pragma unroll
        for (int mt = 0; mt < 4; mt++) {
            float4 av = lds128(Ab + (((((s << 3) | (wr * 4 + mt)) << 5) | lane) << 4));
            a[mt][0] = __float_as_uint(av.x); a[mt][1] = __float_as_uint(av.y);
            a[mt][2] = __float_as_uint(av.z); a[mt][3] = __float_as_uint(av.w);
        }
        uint32_t b[4][2];
#pragma unroll
        for (int pl = 0; pl < 2; pl++) {
            float4 bv = lds128(Bb + (((((s << 3) | (wc * 2 + pl)) << 5) | lane) << 4));
            b[2*pl][0]   = __float_as_uint(bv.x); b[2*pl][1]   = __float_as_uint(bv.y);
            b[2*pl+1][0] = __float_as_uint(bv.z); b[2*pl+1][1] = __float_as_uint(bv.w);
        }
#pragma unroll
        for (int mt = 0; mt < 4; mt++)
#pragma unroll
            for (int nt = 0; nt < 4; nt++)
                mma_tf32(acc[mt][nt], a[mt], b[nt]);
    }
}

// ---------------- row L2-normalize + tf32 round (feature) ----------------
__global__ void norm_rows_kernel(const float* __restrict__ in, float* __restrict__ out)
{
    __shared__ float wsum[4];
    int i = blockIdx.x, t = threadIdx.x;
    float4 v = *(const float4*)&in[(size_t)i * DIMK + t * 4];
    float ss = v.x*v.x + v.y*v.y + v.z*v.z + v.w*v.w;
#pragma unroll
    for (int o = 16; o; o >>= 1) ss += __shfl_xor_sync(0xFFFFFFFFu, ss, o);
    if ((t & 31) == 0) wsum[t >> 5] = ss;
    __syncthreads();
    ss = wsum[0] + wsum[1] + wsum[2] + wsum[3];
    float inv = 1.0f / fmaxf(sqrtf(ss), 1e-12f);
    v.x = tf32r(v.x * inv); v.y = tf32r(v.y * inv);
    v.z = tf32r(v.z * inv); v.w = tf32r(v.w * inv);
    *(float4*)&out[(size_t)i * DIMK + t * 4] = v;
}

// normalize + tf32-round proxy rows in place; zero pad rows [1000,1024)
__global__ void norm_pad_kernel()
{
    __shared__ float wsum[4];
    int i = blockIdx.x, t = threadIdx.x;
    if (i >= CCLS) {
        *(float4*)&g_proxy[(size_t)i * DIMK + t * 4] = make_float4(0.f, 0.f, 0.f, 0.f);
        return;
    }
    float4 v = *(const float4*)&g_proxy[(size_t)i * DIMK + t * 4];
    float ss = v.x*v.x + v.y*v.y + v.z*v.z + v.w*v.w;
#pragma unroll
    for (int o = 16; o; o >>= 1) ss += __shfl_xor_sync(0xFFFFFFFFu, ss, o);
    if ((t & 31) == 0) wsum[t >> 5] = ss;
    __syncthreads();
    ss = wsum[0] + wsum[1] + wsum[2] + wsum[3];
    float inv = 1.0f / fmaxf(sqrtf(ss), 1e-12f);
    v.x = tf32r(v.x * inv); v.y = tf32r(v.y * inv);
    v.z = tf32r(v.z * inv); v.w = tf32r(v.w * inv);
    *(float4*)&g_proxy[(size_t)i * DIMK + t * 4] = v;
}

// ---------------- fp32 SGEMM (small proxy projection; full precision) --------
__global__ __launch_bounds__(256, 2)
void sgemm_nt_kernel(const float* __restrict__ A, const float* __restrict__ B,
                     float* __restrict__ C, int M, int N, int K, int ldc)
{
    __shared__ float As[16][128];
    __shared__ float Bs[16][128];
    int tid = threadIdx.x;
    int tr = tid >> 4, tc = tid & 15;
    int row0 = blockIdx.y * 128, col0 = blockIdx.x * 128;
    int ldrow = tid >> 2, ldk = (tid & 3) * 4;
    float acc[8][8];
#pragma unroll
    for (int x = 0; x < 8; x++)
#pragma unroll
        for (int y = 0; y < 8; y++) acc[x][y] = 0.0f;
    for (int k0 = 0; k0 < K; k0 += 16) {
        __syncthreads();
#pragma unroll
        for (int h = 0; h < 2; h++) {
            int r = ldrow + 64 * h;
            float4 va = make_float4(0,0,0,0), vb = make_float4(0,0,0,0);
            if (row0 + r < M) va = *(const float4*)&A[(size_t)(row0 + r) * K + k0 + ldk];
            if (col0 + r < N) vb = *(const float4*)&B[(size_t)(col0 + r) * K + k0 + ldk];
            As[ldk+0][r]=va.x; As[ldk+1][r]=va.y; As[ldk+2][r]=va.z; As[ldk+3][r]=va.w;
            Bs[ldk+0][r]=vb.x; Bs[ldk+1][r]=vb.y; Bs[ldk+2][r]=vb.z; Bs[ldk+3][r]=vb.w;
        }
        __syncthreads();
#pragma unroll
        for (int kk = 0; kk < 16; kk++) {
            float a[8], b[8];
            *(float4*)&a[0] = *(const float4*)&As[kk][tr*8];
            *(float4*)&a[4] = *(const float4*)&As[kk][tr*8+4];
            *(float4*)&b[0] = *(const float4*)&Bs[kk][tc*8];
            *(float4*)&b[4] = *(const float4*)&Bs[kk][tc*8+4];
#pragma unroll
            for (int x = 0; x < 8; x++)
#pragma unroll
                for (int y = 0; y < 8; y++) acc[x][y] = fmaf(a[x], b[y], acc[x][y]);
        }
    }
#pragma unroll
    for (int x = 0; x < 8; x++) {
        int r = row0 + tr*8 + x;
        if (r < M)
#pragma unroll
            for (int y = 0; y < 8; y++) {
                int cc = col0 + tc*8 + y;
                if (cc < N) C[(size_t)r * ldc + cc] = acc[x][y];
            }
    }
}

// ---------------- pred = feat @ proxy^T, tf32 mma.sync --------------------------
// dyn smem: As0 16K | Bs0 16K | As1 16K | Bs1 16K = 64K
#define PRED_SMEM 65536
__global__ __launch_bounds__(256, 1)
void pred_mma_kernel()
{
    extern __shared__ char smem[];
    uint32_t sb = smem_u32(smem);
    uint32_t Ab[2] = { sb, sb + 32768 };
    uint32_t Bb[2] = { sb + 16384, sb + 49152 };

    int tid = threadIdx.x, w = tid >> 5, lane = tid & 31;
    int wr = w >> 2, wc = w & 3;
    int i0 = blockIdx.y * 128, j0 = blockIdx.x * 128;
    const float* Ar = g_feat  + (size_t)i0 * DIMK;
    const float* Br = g_proxy + (size_t)j0 * DIMK;

    float4 st[8];
    ldg_chunk(Ar, Br, 0, tid, st);
    sts_chunk(Ab[0], Bb[0], tid, st);
    ldg_chunk(Ar, Br, 1, tid, st);
    __syncthreads();

    float acc[4][4][4];
#pragma unroll
    for (int mt = 0; mt < 4; mt++)
#pragma unroll
        for (int nt = 0; nt < 4; nt++)
#pragma unroll
            for (int r = 0; r < 4; r++) acc[mt][nt][r] = 0.0f;

#pragma unroll 1
    for (int k = 0; k < 16; k++) {
        compute_chunk(Ab[k & 1], Bb[k & 1], acc, wr, wc, lane);
        __syncthreads();
        if (k < 15) sts_chunk(Ab[(k + 1) & 1], Bb[(k + 1) & 1], tid, st);
        if (k < 14) ldg_chunk(Ar, Br, k + 2, tid, st);
        __syncthreads();
    }

    // store: row = i0 + wr*64 + mt*16 + (lane>>2) + 8*rh ; col pair at
    // j0 + wc*32 + nt*8 + 2*(lane&3)
#pragma unroll
    for (int mt = 0; mt < 4; mt++)
#pragma unroll
        for (int nt = 0; nt < 4; nt++)
#pragma unroll
            for (int rh = 0; rh < 2; rh++) {
                int row = i0 + wr*64 + mt*16 + (lane >> 2) + rh*8;
                int col = j0 + wc*32 + nt*8 + ((lane & 3) << 1);
                *(float2*)&g_pred[(size_t)row * LDPRED + col] =
                    make_float2(acc[mt][nt][rh*2], acc[mt][nt][rh*2+1]);
            }
}

// ---------------- per-row prob processing ----------------
__global__ void row_prob_kernel(const float* __restrict__ prob, const int* __restrict__ conf)
{
    __shared__ unsigned wbits[WPR];
    __shared__ float sval[256];
    __shared__ int   sidx[256];
    __shared__ float ssc[256];
    __shared__ int   scnt[256];
    int i = blockIdx.x, t = threadIdx.x;
    bool conf_i = conf[i] != 0;
    if (t < WPR) wbits[t] = 0u;
    __syncthreads();
    float best = -INFINITY; int bidx = 0x7FFFFFFF;
    float sc = 0.0f; int cnt = 0;
    for (int c = t; c < CCLS; c += 256) {
        float p = prob[(size_t)i * CCLS + c];
        if (p > best) { best = p; bidx = c; }
        if (p > 0.001f) {
            atomicOr(&wbits[c >> 5], 1u << (c & 31));
            cnt++;
            sc += p * g_pred[(size_t)i * LDPRED + c];
        }
    }
    sval[t] = best; sidx[t] = bidx; ssc[t] = sc; scnt[t] = cnt;
    __syncthreads();
    for (int s = 128; s; s >>= 1) {
        if (t < s) {
            float ov = sval[t+s]; int oi = sidx[t+s];
            if (ov > sval[t] || (ov == sval[t] && oi < sidx[t])) { sval[t] = ov; sidx[t] = oi; }
            ssc[t] += ssc[t+s]; scnt[t] += scnt[t+s];
        }
        __syncthreads();
    }
    if (t == 0) {
        int t1 = sidx[0];
        unsigned sm = 0;
#pragma unroll
        for (int w = 0; w < WPR; w++) {
            unsigned word = conf_i ? (((t1 >> 5) == w) ? (1u << (t1 & 31)) : 0u) : wbits[w];
            g_bits[(size_t)i * WPR + w] = word;
            if (word) sm |= 1u << w;
        }
        g_summ[i] = sm;
        g_pos[i] = conf_i ? g_pred[(size_t)i * LDPRED + t1] : ssc[0];
        g_candcnt[i] = conf_i ? 0 : scnt[0];
        g_notconf[i] = conf_i ? 0 : 1;
    }
}

// ---------------- fused sim: tf32 mma + mask + sum(exp) -------------------------
// dyn smem: As0/Bs0/As1/Bs1 64K | rbits 128*33*4 | cbits 128*33*4 | csum 512 | red 2K
#define OFF_RBITS 65536
#define OFF_CBITS (65536 + 16896)
#define OFF_CSUM  (65536 + 33792)
#define OFF_RED   (65536 + 34304)
#define FUSED_SMEM (65536 + 36352)
__global__ __launch_bounds__(256, 1)
void fused_sim_mma_kernel()
{
    extern __shared__ char smem[];
    uint32_t sb = smem_u32(smem);
    uint32_t Ab[2] = { sb, sb + 32768 };
    uint32_t Bb[2] = { sb + 16384, sb + 49152 };
    unsigned* rbits = (unsigned*)(smem + OFF_RBITS);   // [128][33]
    unsigned* cbits = (unsigned*)(smem + OFF_CBITS);   // [128][33]
    unsigned* csum  = (unsigned*)(smem + OFF_CSUM);    // [128]
    float*    red   = (float*)(smem + OFF_RED);        // [128][4]

    int tid = threadIdx.x, w = tid >> 5, lane = tid & 31;
    int wr = w >> 2, wc = w & 3;
    int i0 = blockIdx.y * 128, j0 = blockIdx.x * 128;
    const float* Ar = g_feat + (size_t)i0 * DIMK;
    const float* Br = g_feat + (size_t)j0 * DIMK;

    // masks
    for (int idx = tid; idx < 128 * WPR; idx += 256) {
        rbits[(idx >> 5) * 33 + (idx & 31)] = g_bits[(size_t)i0 * WPR + idx];
        cbits[(idx >> 5) * 33 + (idx & 31)] = g_bits[(size_t)j0 * WPR + idx];
    }
    if (tid < 128) csum[tid] = g_summ[j0 + tid];

    float4 st[8];
    ldg_chunk(Ar, Br, 0, tid, st);
    sts_chunk(Ab[0], Bb[0], tid, st);
    ldg_chunk(Ar, Br, 1, tid, st);
    __syncthreads();

    float acc[4][4][4];
#pragma unroll
    for (int mt = 0; mt < 4; mt++)
#pragma unroll
        for (int nt = 0; nt < 4; nt++)
#pragma unroll
            for (int r = 0; r < 4; r++) acc[mt][nt][r] = 0.0f;

#pragma unroll 1
    for (int k = 0; k < 16; k++) {
        compute_chunk(Ab[k & 1], Bb[k & 1], acc, wr, wc, lane);
        __syncthreads();
        if (k < 15) sts_chunk(Ab[(k + 1) & 1], Bb[(k + 1) & 1], tid, st);
        if (k < 14) ldg_chunk(Ar, Br, k + 2, tid, st);
        __syncthreads();
    }

    // epilogue: mask + exp, per-row sums
    float rowacc[4][2];
    unsigned rsum[4][2];
#pragma unroll
    for (int mt = 0; mt < 4; mt++)
#pragma unroll
        for (int rh = 0; rh < 2; rh++) {
            rowacc[mt][rh] = 0.0f;
            rsum[mt][rh] = g_summ[i0 + wr*64 + mt*16 + (lane >> 2) + rh*8];
        }

#pragma unroll
    for (int mt = 0; mt < 4; mt++)
#pragma unroll
        for (int nt = 0; nt < 4; nt++)
#pragma unroll
            for (int r = 0; r < 4; r++) {
                int rh = r >> 1;
                int row_l = wr*64 + mt*16 + (lane >> 2) + rh*8;
                int col_l = wc*32 + nt*8 + ((lane & 3) << 1) + (r & 1);
                float v = acc[mt][nt][r];
                if (v >= 1e-6f) {
                    unsigned hit = rsum[mt][rh] & csum[col_l];
                    bool masked = false;
                    while (hit) {
                        int wd = __ffs((int)hit) - 1;
                        if (rbits[row_l*33 + wd] & cbits[col_l*33 + wd]) { masked = true; break; }
                        hit &= hit - 1;
                    }
                    if (!masked) rowacc[mt][rh] += __expf(v);
                }
            }

#pragma unroll
    for (int mt = 0; mt < 4; mt++)
#pragma unroll
        for (int rh = 0; rh < 2; rh++) {
            float v = rowacc[mt][rh];
            v += __shfl_xor_sync(0xFFFFFFFFu, v, 1);
            v += __shfl_xor_sync(0xFFFFFFFFu, v, 2);
            if ((lane & 3) == 0) {
                int row_l = wr*64 + mt*16 + (lane >> 2) + rh*8;
                red[row_l * 4 + wc] = v;
            }
        }
    __syncthreads();
    if (tid < 128) {
        float s = red[tid*4] + red[tid*4+1] + red[tid*4+2] + red[tid*4+3];
        g_partial[(size_t)blockIdx.x * NROWS + i0 + tid] = s;
    }
}

// ---------------- final reduction ----------------
__global__ void final_kernel(float* __restrict__ out)
{
    __shared__ float sl[256];
    __shared__ int   sc[256];
    __shared__ int   sn[256];
    int t = threadIdx.x;
    float lacc = 0.0f; int cacc = 0, nacc = 0;
    for (int i = t; i < NROWS; i += 256) {
        float pos = g_pos[i];
        float S = expf(pos);
#pragma unroll
        for (int ch = 0; ch < 64; ch++) S += g_partial[(size_t)ch * NROWS + i];
        lacc += logf(S) - pos;
        cacc += g_candcnt[i];
        nacc += g_notconf[i];
    }
    sl[t] = lacc; sc[t] = cacc; sn[t] = nacc;
    __syncthreads();
    for (int s = 128; s; s >>= 1) {
        if (t < s) { sl[t] += sl[t+s]; sc[t] += sc[t+s]; sn[t] += sn[t+s]; }
        __syncthreads();
    }
    if (t == 0) {
        out[0] = sl[0] / (float)NROWS;
        out[1] = (sn[0] > 0) ? ((float)sc[0] / (float)sn[0]) : 0.0f;
    }
}

// ---------------- launch ----------------
extern "C" void kernel_launch(void* const* d_in, const int* in_sizes, int n_in,
                              void* d_out, int out_size)
{
    const float* feature   = (const float*)d_in[0];
    const float* proxy_raw = (const float*)d_in[1];
    const float* cPw       = (const float*)d_in[2];
    const float* prob      = (const float*)d_in[3];
    const int*   conf      = (const int*)d_in[4];
    float* out = (float*)d_out;

    void *p_feat, *p_proxy;
    cudaGetSymbolAddress(&p_feat, g_feat);
    cudaGetSymbolAddress(&p_proxy, g_proxy);

    cudaFuncSetAttribute(pred_mma_kernel, cudaFuncAttributeMaxDynamicSharedMemorySize, PRED_SMEM);
    cudaFuncSetAttribute(fused_sim_mma_kernel, cudaFuncAttributeMaxDynamicSharedMemorySize, FUSED_SMEM);

    // 1) feat = tf32(l2norm(feature))
    norm_rows_kernel<<<NROWS, 128>>>(feature, (float*)p_feat);
    // 2) proxy = proxy_raw @ cP_weight^T (fp32)
    sgemm_nt_kernel<<<dim3(4, 8), 256>>>(proxy_raw, cPw, (float*)p_proxy, CCLS, DIMK, DIMK, DIMK);
    // 3) normalize + tf32-round + pad proxy
    norm_pad_kernel<<<NPAD, 128>>>();
    // 4) pred = feat @ proxy^T (tf32 mma.sync)
    pred_mma_kernel<<<dim3(NPAD / 128, NROWS / 128), 256, PRED_SMEM>>>();
    // 5) per-row prob/bits/pos
    row_prob_kernel<<<NROWS, 256>>>(prob, conf);
    // 6) fused sim (tf32 mma.sync) + mask + exp-sum
    fused_sim_mma_kernel<<<dim3(NROWS / 128, NROWS / 128), 256, FUSED_SMEM>>>();
    // 7) loss + sc_num
    final_kernel<<<1, 256>>>(out);
}

// round 4
// speedup vs baseline: 2.9950x; 2.9053x over previous
#include <cuda_runtime.h>
#include <math.h>
#include <stdint.h>

// ---------------- problem constants ----------------
#define NROWS  8192
#define DIMK   512
#define CCLS   1000
#define LDPRED 1024
#define WPR    32
#define NPAD   1024
#define NBLK   64            // NROWS / 128
#define NCHUNK 16            // DIMK / 32

// ---------------- device scratch (static) ----------------
__device__ float    g_featA[NROWS * DIMK];       // A-fragment-ordered feat
__device__ float    g_featB[NROWS * DIMK];       // B-fragment-ordered feat
__device__ float    g_proxy[NPAD * DIMK];        // natural proxies (intermediate)
__device__ float    g_proxyB[NPAD * DIMK];       // B-fragment-ordered proxies
__device__ float    g_pred[NROWS * LDPRED];      // feat @ proxy^T
__device__ unsigned g_bits[NROWS * WPR];
__device__ unsigned g_summ[NROWS];
__device__ float    g_pos[NROWS];
__device__ int      g_candcnt[NROWS];
__device__ int      g_notconf[NROWS];
__device__ float    g_prow[NBLK * NROWS];        // row partials, slot = bj
__device__ float    g_pcol[NBLK * NROWS];        // col partials, slot = bi

// ---------------- small helpers ----------------
__device__ __forceinline__ uint32_t smem_u32(const void* p) {
    uint32_t a;
    asm("{ .reg .u64 t; cvta.to.shared.u64 t, %1; cvt.u32.u64 %0, t; }" : "=r"(a) : "l"(p));
    return a;
}
__device__ __forceinline__ float4 lds128(uint32_t a) {
    float4 r;
    asm volatile("ld.shared.v4.f32 {%0,%1,%2,%3}, [%4];"
                 : "=f"(r.x), "=f"(r.y), "=f"(r.z), "=f"(r.w) : "r"(a));
    return r;
}
__device__ __forceinline__ float tf32r(float x) {
    uint32_t u;
    asm("cvt.rna.tf32.f32 %0, %1;" : "=r"(u) : "f"(x));
    return __uint_as_float(u);
}
__device__ __forceinline__ void cp16(uint32_t dst, const void* src) {
    asm volatile("cp.async.cg.shared.global [%0], [%1], 16;" :: "r"(dst), "l"(src));
}
__device__ __forceinline__ void cp_commit() { asm volatile("cp.async.commit_group;"); }
template <int N> __device__ __forceinline__ void cp_wait() {
    asm volatile("cp.async.wait_group %0;" :: "n"(N) : "memory");
}
__device__ __forceinline__ void mma_tf32(float c[4], const uint32_t a[4], const uint32_t b[2]) {
    asm volatile(
        "mma.sync.aligned.m16n8k8.row.col.f32.tf32.tf32.f32 "
        "{%0,%1,%2,%3}, {%4,%5,%6,%7}, {%8,%9}, {%0,%1,%2,%3};"
        : "+f"(c[0]), "+f"(c[1]), "+f"(c[2]), "+f"(c[3])
        : "r"(a[0]), "r"(a[1]), "r"(a[2]), "r"(a[3]), "r"(b[0]), "r"(b[1]));
}

// ---------------- fragment blob index math ----------------
// A blob (per 128-row block, per k-chunk of 32): 4096 floats.
//   idx = (((s<<3)|m)<<5 | laneA)*4 + regA
// B blob: idx = (((s<<3)|pair)<<5 | laneB)*4 + slotB
__device__ __forceinline__ int a_blob_idx(int r, int kl) {
    int s = kl >> 3, kk = kl & 7, m = r >> 4, rr = r & 15;
    int lane = ((rr & 7) << 2) | (kk & 3);
    int reg  = (rr >> 3) | ((kk >> 2) << 1);
    return ((((s << 3) | m) << 5) | lane) * 4 + reg;
}
__device__ __forceinline__ int b_blob_idx(int r, int kl) {
    int s = kl >> 3, kk = kl & 7, g = r >> 3, nl = r & 7;
    int lane = (nl << 2) | (kk & 3);
    int slot = ((g & 1) << 1) | (kk >> 2);
    int pair = g >> 1;
    return ((((s << 3) | pair) << 5) | lane) * 4 + slot;
}

// ---------------- shared GEMM core ----------------
// stage: A 16KB @ +0, B 16KB @ +16384. 3 stages x 32KB.
__device__ __forceinline__ void ldg_stage(uint32_t st, const float* blobA,
                                          const float* blobB, int kc, int tid)
{
    const char* a = (const char*)blobA + (size_t)kc * 16384;
    const char* b = (const char*)blobB + (size_t)kc * 16384;
#pragma unroll
    for (int ii = 0; ii < 4; ii++) {
        int o = (tid + (ii << 8)) << 4;
        cp16(st + o, a + o);
        cp16(st + 16384 + o, b + o);
    }
    cp_commit();
}

__device__ __forceinline__ void compute_chunk(uint32_t Ab, uint32_t Bb,
                                              float acc[4][4][4], int wr, int wc, int lane)
{
#pragma unroll
    for (int s = 0; s < 4; s++) {
        uint32_t a[4][4];
#pragma unroll
        for (int mt = 0; mt < 4; mt++) {
            float4 av = lds128(Ab + (((((s << 3) | (wr * 4 + mt)) << 5) | lane) << 4));
            a[mt][0] = __float_as_uint(av.x); a[mt][1] = __float_as_uint(av.y);
            a[mt][2] = __float_as_uint(av.z); a[mt][3] = __float_as_uint(av.w);
        }
        uint32_t b[4][2];
#pragma unroll
        for (int pl = 0; pl < 2; pl++) {
            float4 bv = lds128(Bb + (((((s << 3) | (wc * 2 + pl)) << 5) | lane) << 4));
            b[2*pl][0]   = __float_as_uint(bv.x); b[2*pl][1]   = __float_as_uint(bv.y);
            b[2*pl+1][0] = __float_as_uint(bv.z); b[2*pl+1][1] = __float_as_uint(bv.w);
        }
#pragma unroll
        for (int mt = 0; mt < 4; mt++)
#pragma unroll
            for (int nt = 0; nt < 4; nt++)
                mma_tf32(acc[mt][nt], a[mt], b[nt]);
    }
}

__device__ __forceinline__ void gemm_mainloop(const float* blobA, const float* blobB,
                                              uint32_t sb, int tid, int wr, int wc, int lane,
                                              float acc[4][4][4])
{
    ldg_stage(sb,         blobA, blobB, 0, tid);
    ldg_stage(sb + 32768, blobA, blobB, 1, tid);
    ldg_stage(sb + 65536, blobA, blobB, 2, tid);
#pragma unroll 1
    for (int k = 0; k < NCHUNK; k++) {
        if (k < NCHUNK - 2)      cp_wait<2>();
        else if (k == NCHUNK-2)  cp_wait<1>();
        else                     cp_wait<0>();
        __syncthreads();
        uint32_t st = sb + (uint32_t)(k % 3) * 32768u;
        compute_chunk(st, st + 16384, acc, wr, wc, lane);
        __syncthreads();
        if (k + 3 < NCHUNK) ldg_stage(st, blobA, blobB, k + 3, tid);
    }
}

// ---------------- norm + scatter into fragment blobs (feat) ----------------
__global__ void norm_feat_kernel(const float* __restrict__ in)
{
    __shared__ float wsum[4];
    int i = blockIdx.x, t = threadIdx.x;
    float4 v = *(const float4*)&in[(size_t)i * DIMK + t * 4];
    float ss = v.x*v.x + v.y*v.y + v.z*v.z + v.w*v.w;
#pragma unroll
    for (int o = 16; o; o >>= 1) ss += __shfl_xor_sync(0xFFFFFFFFu, ss, o);
    if ((t & 31) == 0) wsum[t >> 5] = ss;
    __syncthreads();
    ss = wsum[0] + wsum[1] + wsum[2] + wsum[3];
    float inv = 1.0f / fmaxf(sqrtf(ss), 1e-12f);
    float vv[4] = { tf32r(v.x*inv), tf32r(v.y*inv), tf32r(v.z*inv), tf32r(v.w*inv) };

    int blk = i >> 7, r = i & 127;
    size_t base = (size_t)blk * NCHUNK * 4096;
#pragma unroll
    for (int j = 0; j < 4; j++) {
        int k = t * 4 + j, kc = k >> 5, kl = k & 31;
        g_featA[base + (size_t)kc * 4096 + a_blob_idx(r, kl)] = vv[j];
        g_featB[base + (size_t)kc * 4096 + b_blob_idx(r, kl)] = vv[j];
    }
}

// normalize proxy rows, scatter into B blob; pad rows -> zeros
__global__ void norm_pad_kernel()
{
    __shared__ float wsum[4];
    int i = blockIdx.x, t = threadIdx.x;
    float vv[4] = {0.f, 0.f, 0.f, 0.f};
    if (i < CCLS) {
        float4 v = *(const float4*)&g_proxy[(size_t)i * DIMK + t * 4];
        float ss = v.x*v.x + v.y*v.y + v.z*v.z + v.w*v.w;
#pragma unroll
        for (int o = 16; o; o >>= 1) ss += __shfl_xor_sync(0xFFFFFFFFu, ss, o);
        if ((t & 31) == 0) wsum[t >> 5] = ss;
        __syncthreads();
        ss = wsum[0] + wsum[1] + wsum[2] + wsum[3];
        float inv = 1.0f / fmaxf(sqrtf(ss), 1e-12f);
        vv[0] = tf32r(v.x*inv); vv[1] = tf32r(v.y*inv);
        vv[2] = tf32r(v.z*inv); vv[3] = tf32r(v.w*inv);
    }
    int blk = i >> 7, r = i & 127;
    size_t base = (size_t)blk * NCHUNK * 4096;
#pragma unroll
    for (int j = 0; j < 4; j++) {
        int k = t * 4 + j, kc = k >> 5, kl = k & 31;
        g_proxyB[base + (size_t)kc * 4096 + b_blob_idx(r, kl)] = vv[j];
    }
}

// ---------------- fp32 SGEMM (small proxy projection) ----------------
__global__ __launch_bounds__(256, 2)
void sgemm_nt_kernel(const float* __restrict__ A, const float* __restrict__ B,
                     float* __restrict__ C, int M, int N, int K, int ldc)
{
    __shared__ float As[16][128];
    __shared__ float Bs[16][128];
    int tid = threadIdx.x;
    int tr = tid >> 4, tc = tid & 15;
    int row0 = blockIdx.y * 128, col0 = blockIdx.x * 128;
    int ldrow = tid >> 2, ldk = (tid & 3) * 4;
    float acc[8][8];
#pragma unroll
    for (int x = 0; x < 8; x++)
#pragma unroll
        for (int y = 0; y < 8; y++) acc[x][y] = 0.0f;
    for (int k0 = 0; k0 < K; k0 += 16) {
        __syncthreads();
#pragma unroll
        for (int h = 0; h < 2; h++) {
            int r = ldrow + 64 * h;
            float4 va = make_float4(0,0,0,0), vb = make_float4(0,0,0,0);
            if (row0 + r < M) va = *(const float4*)&A[(size_t)(row0 + r) * K + k0 + ldk];
            if (col0 + r < N) vb = *(const float4*)&B[(size_t)(col0 + r) * K + k0 + ldk];
            As[ldk+0][r]=va.x; As[ldk+1][r]=va.y; As[ldk+2][r]=va.z; As[ldk+3][r]=va.w;
            Bs[ldk+0][r]=vb.x; Bs[ldk+1][r]=vb.y; Bs[ldk+2][r]=vb.z; Bs[ldk+3][r]=vb.w;
        }
        __syncthreads();
#pragma unroll
        for (int kk = 0; kk < 16; kk++) {
            float a[8], b[8];
            *(float4*)&a[0] = *(const float4*)&As[kk][tr*8];
            *(float4*)&a[4] = *(const float4*)&As[kk][tr*8+4];
            *(float4*)&b[0] = *(const float4*)&Bs[kk][tc*8];
            *(float4*)&b[4] = *(const float4*)&Bs[kk][tc*8+4];
#pragma unroll
            for (int x = 0; x < 8; x++)
#pragma unroll
                for (int y = 0; y < 8; y++) acc[x][y] = fmaf(a[x], b[y], acc[x][y]);
        }
    }
#pragma unroll
    for (int x = 0; x < 8; x++) {
        int r = row0 + tr*8 + x;
        if (r < M)
#pragma unroll
            for (int y = 0; y < 8; y++) {
                int cc = col0 + tc*8 + y;
                if (cc < N) C[(size_t)r * ldc + cc] = acc[x][y];
            }
    }
}

// ---------------- pred = feat @ proxy^T (tf32 mma, pipelined) ----------------
#define GEMM_SMEM 98304
__global__ __launch_bounds__(256, 2)
void pred_mma_kernel()
{
    extern __shared__ char smem[];
    uint32_t sb = smem_u32(smem);
    int tid = threadIdx.x, w = tid >> 5, lane = tid & 31;
    int wr = w >> 2, wc = w & 3;
    int bi = blockIdx.y, bj = blockIdx.x;
    const float* blobA = g_featA  + (size_t)bi * NCHUNK * 4096;
    const float* blobB = g_proxyB + (size_t)bj * NCHUNK * 4096;

    float acc[4][4][4];
#pragma unroll
    for (int mt = 0; mt < 4; mt++)
#pragma unroll
        for (int nt = 0; nt < 4; nt++)
#pragma unroll
            for (int r = 0; r < 4; r++) acc[mt][nt][r] = 0.0f;

    gemm_mainloop(blobA, blobB, sb, tid, wr, wc, lane, acc);

#pragma unroll
    for (int mt = 0; mt < 4; mt++)
#pragma unroll
        for (int nt = 0; nt < 4; nt++)
#pragma unroll
            for (int rh = 0; rh < 2; rh++) {
                int row = bi*128 + wr*64 + mt*16 + (lane >> 2) + rh*8;
                int col = bj*128 + wc*32 + nt*8 + ((lane & 3) << 1);
                *(float2*)&g_pred[(size_t)row * LDPRED + col] =
                    make_float2(acc[mt][nt][rh*2], acc[mt][nt][rh*2+1]);
            }
}

// ---------------- per-row prob processing ----------------
__global__ void row_prob_kernel(const float* __restrict__ prob, const int* __restrict__ conf)
{
    __shared__ unsigned wbits[WPR];
    __shared__ float sval[256];
    __shared__ int   sidx[256];
    __shared__ float ssc[256];
    __shared__ int   scnt[256];
    int i = blockIdx.x, t = threadIdx.x;
    bool conf_i = conf[i] != 0;
    if (t < WPR) wbits[t] = 0u;
    __syncthreads();
    float best = -INFINITY; int bidx = 0x7FFFFFFF;
    float sc = 0.0f; int cnt = 0;
    for (int c = t; c < CCLS; c += 256) {
        float p = prob[(size_t)i * CCLS + c];
        if (p > best) { best = p; bidx = c; }
        if (p > 0.001f) {
            atomicOr(&wbits[c >> 5], 1u << (c & 31));
            cnt++;
            sc += p * g_pred[(size_t)i * LDPRED + c];
        }
    }
    sval[t] = best; sidx[t] = bidx; ssc[t] = sc; scnt[t] = cnt;
    __syncthreads();
    for (int s = 128; s; s >>= 1) {
        if (t < s) {
            float ov = sval[t+s]; int oi = sidx[t+s];
            if (ov > sval[t] || (ov == sval[t] && oi < sidx[t])) { sval[t] = ov; sidx[t] = oi; }
            ssc[t] += ssc[t+s]; scnt[t] += scnt[t+s];
        }
        __syncthreads();
    }
    if (t == 0) {
        int t1 = sidx[0];
        unsigned sm = 0;
#pragma unroll
        for (int w = 0; w < WPR; w++) {
            unsigned word = conf_i ? (((t1 >> 5) == w) ? (1u << (t1 & 31)) : 0u) : wbits[w];
            g_bits[(size_t)i * WPR + w] = word;
            if (word) sm |= 1u << w;
        }
        g_summ[i] = sm;
        g_pos[i] = conf_i ? g_pred[(size_t)i * LDPRED + t1] : ssc[0];
        g_candcnt[i] = conf_i ? 0 : scnt[0];
        g_notconf[i] = conf_i ? 0 : 1;
    }
}

// ---------------- fused sim: upper-triangle tiles, mask + exp ----------------
__global__ __launch_bounds__(256, 2)
void fused_sim_mma_kernel()
{
    extern __shared__ char smem[];
    uint32_t sb = smem_u32(smem);
    int tid = threadIdx.x, w = tid >> 5, lane = tid & 31;
    int wr = w >> 2, wc = w & 3;
    int bi = blockIdx.y, bj = blockIdx.x;

    if (bj < bi) {              // idle tile: deterministically zero unused slots
        if (tid < 128) {
            g_prow[(size_t)bj * NROWS + bi*128 + tid] = 0.0f;
            g_pcol[(size_t)bi * NROWS + bj*128 + tid] = 0.0f;
        }
        return;
    }
    bool offdiag = (bj != bi);
    if (!offdiag && tid < 128)
        g_pcol[(size_t)bi * NROWS + bj*128 + tid] = 0.0f;

    const float* blobA = g_featA + (size_t)bi * NCHUNK * 4096;
    const float* blobB = g_featB + (size_t)bj * NCHUNK * 4096;

    float acc[4][4][4];
#pragma unroll
    for (int mt = 0; mt < 4; mt++)
#pragma unroll
        for (int nt = 0; nt < 4; nt++)
#pragma unroll
            for (int r = 0; r < 4; r++) acc[mt][nt][r] = 0.0f;

    gemm_mainloop(blobA, blobB, sb, tid, wr, wc, lane, acc);

    // ---- epilogue: overlay masks on stage smem (mainloop ended with barrier)
    unsigned* rbits = (unsigned*)smem;                 // [128][33]
    unsigned* cbits = rbits + 128 * 33;                // [128][33]
    unsigned* csum  = cbits + 128 * 33;                // [128]
    float*    red     = (float*)(csum + 128);          // [128][4]
    float*    colred  = red + 512;                     // [128][2]

    for (int idx = tid; idx < 128 * WPR; idx += 256) {
        rbits[(idx >> 5) * 33 + (idx & 31)] = g_bits[(size_t)(bi*128) * WPR + idx];
        cbits[(idx >> 5) * 33 + (idx & 31)] = g_bits[(size_t)(bj*128) * WPR + idx];
    }
    if (tid < 128) csum[tid] = g_summ[bj*128 + tid];
    __syncthreads();

    float rowacc[4][2], colacc[4][2];
    unsigned rsum[4][2];
#pragma unroll
    for (int mt = 0; mt < 4; mt++)
#pragma unroll
        for (int rh = 0; rh < 2; rh++) {
            rowacc[mt][rh] = 0.0f;
            rsum[mt][rh] = g_summ[bi*128 + wr*64 + mt*16 + (lane >> 2) + rh*8];
        }
#pragma unroll
    for (int nt = 0; nt < 4; nt++)
#pragma unroll
        for (int cb = 0; cb < 2; cb++) colacc[nt][cb] = 0.0f;

#pragma unroll
    for (int mt = 0; mt < 4; mt++)
#pragma unroll
        for (int nt = 0; nt < 4; nt++)
#pragma unroll
            for (int r = 0; r < 4; r++) {
                int rh = r >> 1, cb = r & 1;
                float v = acc[mt][nt][r];
                if (v >= 1e-6f) {
                    int row_l = wr*64 + mt*16 + (lane >> 2) + rh*8;
                    int col_l = wc*32 + nt*8 + ((lane & 3) << 1) + cb;
                    unsigned hit = rsum[mt][rh] & csum[col_l];
                    bool masked = false;
                    while (hit) {
                        int wd = __ffs((int)hit) - 1;
                        if (rbits[row_l*33 + wd] & cbits[col_l*33 + wd]) { masked = true; break; }
                        hit &= hit - 1;
                    }
                    if (!masked) {
                        float e = __expf(v);
                        rowacc[mt][rh] += e;
                        colacc[nt][cb] += e;
                    }
                }
            }

    // row reduce (across lane&3 quad, then 4 wc warps)
#pragma unroll
    for (int mt = 0; mt < 4; mt++)
#pragma unroll
        for (int rh = 0; rh < 2; rh++) {
            float v = rowacc[mt][rh];
            v += __shfl_xor_sync(0xFFFFFFFFu, v, 1);
            v += __shfl_xor_sync(0xFFFFFFFFu, v, 2);
            if ((lane & 3) == 0)
                red[(wr*64 + mt*16 + (lane >> 2) + rh*8) * 4 + wc] = v;
        }
    // col reduce (across lane>>2 octet, then 2 wr warps)
#pragma unroll
    for (int nt = 0; nt < 4; nt++)
#pragma unroll
        for (int cb = 0; cb < 2; cb++) {
            float v = colacc[nt][cb];
            v += __shfl_xor_sync(0xFFFFFFFFu, v, 4);
            v += __shfl_xor_sync(0xFFFFFFFFu, v, 8);
            v += __shfl_xor_sync(0xFFFFFFFFu, v, 16);
            if ((lane >> 2) == 0)
                colred[(wc*32 + nt*8 + ((lane & 3) << 1) + cb) * 2 + wr] = v;
        }
    __syncthreads();
    if (tid < 128) {
        float s = red[tid*4] + red[tid*4+1] + red[tid*4+2] + red[tid*4+3];
        g_prow[(size_t)bj * NROWS + bi*128 + tid] = s;
        if (offdiag)
            g_pcol[(size_t)bi * NROWS + bj*128 + tid] = colred[tid*2] + colred[tid*2+1];
    }
}

// ---------------- final reduction ----------------
__global__ void final_kernel(float* __restrict__ out)
{
    __shared__ float sl[256];
    __shared__ int   sc[256];
    __shared__ int   sn[256];
    int t = threadIdx.x;
    float lacc = 0.0f; int cacc = 0, nacc = 0;
    for (int i = t; i < NROWS; i += 256) {
        float pos = g_pos[i];
        float S = expf(pos);
#pragma unroll 8
        for (int s = 0; s < NBLK; s++) S += g_prow[(size_t)s * NROWS + i];
#pragma unroll 8
        for (int s = 0; s < NBLK; s++) S += g_pcol[(size_t)s * NROWS + i];
        lacc += logf(S) - pos;
        cacc += g_candcnt[i];
        nacc += g_notconf[i];
    }
    sl[t] = lacc; sc[t] = cacc; sn[t] = nacc;
    __syncthreads();
    for (int s = 128; s; s >>= 1) {
        if (t < s) { sl[t] += sl[t+s]; sc[t] += sc[t+s]; sn[t] += sn[t+s]; }
        __syncthreads();
    }
    if (t == 0) {
        out[0] = sl[0] / (float)NROWS;
        out[1] = (sn[0] > 0) ? ((float)sc[0] / (float)sn[0]) : 0.0f;
    }
}

// ---------------- launch ----------------
extern "C" void kernel_launch(void* const* d_in, const int* in_sizes, int n_in,
                              void* d_out, int out_size)
{
    const float* feature   = (const float*)d_in[0];
    const float* proxy_raw = (const float*)d_in[1];
    const float* cPw       = (const float*)d_in[2];
    const float* prob      = (const float*)d_in[3];
    const int*   conf      = (const int*)d_in[4];
    float* out = (float*)d_out;

    void* p_proxy;
    cudaGetSymbolAddress(&p_proxy, g_proxy);

    cudaFuncSetAttribute(pred_mma_kernel, cudaFuncAttributeMaxDynamicSharedMemorySize, GEMM_SMEM);
    cudaFuncSetAttribute(fused_sim_mma_kernel, cudaFuncAttributeMaxDynamicSharedMemorySize, GEMM_SMEM);

    // 1) proxy = proxy_raw @ cP_weight^T (fp32)
    sgemm_nt_kernel<<<dim3(4, 8), 256>>>(proxy_raw, cPw, (float*)p_proxy, CCLS, DIMK, DIMK, DIMK);
    // 2) feat: normalize + tf32 round + scatter to A/B fragment blobs
    norm_feat_kernel<<<NROWS, 128>>>(feature);
    // 3) proxy: normalize + tf32 round + scatter to B blob (pad rows zero)
    norm_pad_kernel<<<NPAD, 128>>>();
    // 4) pred = feat @ proxy^T
    pred_mma_kernel<<<dim3(NPAD / 128, NROWS / 128), 256, GEMM_SMEM>>>();
    // 5) per-row prob/bits/pos
    row_prob_kernel<<<NROWS, 256>>>(prob, conf);
    // 6) fused sim (upper triangle) + mask + exp partials
    fused_sim_mma_kernel<<<dim3(NBLK, NBLK), 256, GEMM_SMEM>>>();
    // 7) loss + sc_num
    final_kernel<<<1, 256>>>(out);
}

// round 5
// speedup vs baseline: 3.7590x; 1.2551x over previous
#include <cuda_runtime.h>
#include <math.h>
#include <stdint.h>

// ---------------- problem constants ----------------
#define NROWS  8192
#define DIMK   512
#define CCLS   1000
#define LDPRED 1024
#define WPR    32
#define NPAD   1024
#define NBLK   64            // NROWS / 128
#define NCHUNK 16            // DIMK / 32

// ---------------- device scratch (static) ----------------
__device__ float    g_featA[NROWS * DIMK];       // A-fragment-ordered feat
__device__ float    g_featB[NROWS * DIMK];       // B-fragment-ordered feat
__device__ float    g_proxy[NPAD * DIMK];        // projected proxies (natural layout)
__device__ float    g_proxyB[NPAD * DIMK];       // B-fragment-ordered proxies
__device__ float    g_pred[NROWS * LDPRED];      // feat @ proxy^T
__device__ float    g_inv[NROWS];                // 1/||feature row||
__device__ float    g_invp[NPAD];                // 1/||proxy row||
__device__ unsigned g_bits[NROWS * WPR];
__device__ unsigned g_summ[NROWS];
__device__ float    g_pos[NROWS];
__device__ int      g_candcnt[NROWS];
__device__ int      g_notconf[NROWS];
__device__ float    g_part[NBLK * NROWS];        // merged exp-sum partials (disjoint slots)
__device__ float    g_redl[32];
__device__ int      g_redc[32];
__device__ int      g_redn[32];

// ---------------- small helpers ----------------
__device__ __forceinline__ uint32_t smem_u32(const void* p) {
    uint32_t a;
    asm("{ .reg .u64 t; cvta.to.shared.u64 t, %1; cvt.u32.u64 %0, t; }" : "=r"(a) : "l"(p));
    return a;
}
__device__ __forceinline__ float4 lds128(uint32_t a) {
    float4 r;
    asm volatile("ld.shared.v4.f32 {%0,%1,%2,%3}, [%4];"
                 : "=f"(r.x), "=f"(r.y), "=f"(r.z), "=f"(r.w) : "r"(a));
    return r;
}
__device__ __forceinline__ float tf32r(float x) {
    uint32_t u;
    asm("cvt.rna.tf32.f32 %0, %1;" : "=r"(u) : "f"(x));
    return __uint_as_float(u);
}
__device__ __forceinline__ void cp16(uint32_t dst, const void* src) {
    asm volatile("cp.async.cg.shared.global [%0], [%1], 16;" :: "r"(dst), "l"(src));
}
__device__ __forceinline__ void cp_commit() { asm volatile("cp.async.commit_group;"); }
template <int N> __device__ __forceinline__ void cp_wait() {
    asm volatile("cp.async.wait_group %0;" :: "n"(N) : "memory");
}
__device__ __forceinline__ void mma_tf32(float c[4], const uint32_t a[4], const uint32_t b[2]) {
    asm volatile(
        "mma.sync.aligned.m16n8k8.row.col.f32.tf32.tf32.f32 "
        "{%0,%1,%2,%3}, {%4,%5,%6,%7}, {%8,%9}, {%0,%1,%2,%3};"
        : "+f"(c[0]), "+f"(c[1]), "+f"(c[2]), "+f"(c[3])
        : "r"(a[0]), "r"(a[1]), "r"(a[2]), "r"(a[3]), "r"(b[0]), "r"(b[1]));
}

// ---------------- shared GEMM core ----------------
// stage: A 16KB @ +0, B 16KB @ +16384. 3 stages x 32KB, single-sync pipeline.
__device__ __forceinline__ void ldg_stage(uint32_t st, const float* blobA,
                                          const float* blobB, int kc, int tid)
{
    const char* a = (const char*)blobA + (size_t)kc * 16384;
    const char* b = (const char*)blobB + (size_t)kc * 16384;
#pragma unroll
    for (int ii = 0; ii < 4; ii++) {
        int o = (tid + (ii << 8)) << 4;
        cp16(st + o, a + o);
        cp16(st + 16384 + o, b + o);
    }
    cp_commit();
}

__device__ __forceinline__ void compute_chunk(uint32_t Ab, uint32_t Bb,
                                              float acc[4][4][4], int wr, int wc, int lane)
{
#pragma unroll
    for (int s = 0; s < 4; s++) {
        uint32_t a[4][4];
#pragma unroll
        for (int mt = 0; mt < 4; mt++) {
            float4 av = lds128(Ab + (((((s << 3) | (wr * 4 + mt)) << 5) | lane) << 4));
            a[mt][0] = __float_as_uint(av.x); a[mt][1] = __float_as_uint(av.y);
            a[mt][2] = __float_as_uint(av.z); a[mt][3] = __float_as_uint(av.w);
        }
        uint32_t b[4][2];
#pragma unroll
        for (int pl = 0; pl < 2; pl++) {
            float4 bv = lds128(Bb + (((((s << 3) | (wc * 2 + pl)) << 5) | lane) << 4));
            b[2*pl][0]   = __float_as_uint(bv.x); b[2*pl][1]   = __float_as_uint(bv.y);
            b[2*pl+1][0] = __float_as_uint(bv.z); b[2*pl+1][1] = __float_as_uint(bv.w);
        }
#pragma unroll
        for (int mt = 0; mt < 4; mt++)
#pragma unroll
            for (int nt = 0; nt < 4; nt++)
                mma_tf32(acc[mt][nt], a[mt], b[nt]);
    }
}

__device__ __forceinline__ void gemm_mainloop(const float* blobA, const float* blobB,
                                              uint32_t sb, int tid, int wr, int wc, int lane,
                                              float acc[4][4][4])
{
    ldg_stage(sb,         blobA, blobB, 0, tid);
    ldg_stage(sb + 32768, blobA, blobB, 1, tid);
#pragma unroll 1
    for (int k = 0; k < NCHUNK; k++) {
        if (k < NCHUNK - 1) cp_wait<1>(); else cp_wait<0>();
        __syncthreads();
        // buffer (k+2)%3 == (k-1)%3: consumed by all warps before this barrier
        if (k + 2 < NCHUNK)
            ldg_stage(sb + (uint32_t)((k + 2) % 3) * 32768u, blobA, blobB, k + 2, tid);
        uint32_t st = sb + (uint32_t)(k % 3) * 32768u;
        compute_chunk(st, st + 16384, acc, wr, wc, lane);
    }
}

// ---------------- inverse L2 norms (one warp per row) ----------------
__global__ void inv_norm_kernel(const float* __restrict__ in, float* __restrict__ outinv,
                                int nrows)
{
    int row = blockIdx.x * 8 + (threadIdx.x >> 5);
    int lane = threadIdx.x & 31;
    if (row >= nrows) return;
    const float4* p = (const float4*)(in + (size_t)row * DIMK);
    float ss = 0.0f;
#pragma unroll
    for (int q = 0; q < 4; q++) {
        float4 v = p[lane + 32 * q];
        ss += v.x*v.x + v.y*v.y + v.z*v.z + v.w*v.w;
    }
#pragma unroll
    for (int o = 16; o; o >>= 1) ss += __shfl_xor_sync(0xFFFFFFFFu, ss, o);
    if (lane == 0) outinv[row] = 1.0f / fmaxf(sqrtf(ss), 1e-12f);
}

// ---------------- coalesced fragmentize: feat -> A & B blobs ----------------
__global__ __launch_bounds__(256)
void frag_feat_kernel(const float* __restrict__ in)
{
    __shared__ float tile[128][33];
    int kc = blockIdx.x, blk = blockIdx.y;
    int t = threadIdx.x;
    int row = t >> 1, half = t & 1;
    float inv = g_inv[blk * 128 + row];
    const float* src = in + (size_t)(blk * 128 + row) * DIMK + kc * 32 + half * 16;
#pragma unroll
    for (int q = 0; q < 4; q++) {
        float4 v = *(const float4*)(src + q * 4);
        int c = half * 16 + q * 4;
        tile[row][c+0] = tf32r(v.x * inv); tile[row][c+1] = tf32r(v.y * inv);
        tile[row][c+2] = tf32r(v.z * inv); tile[row][c+3] = tf32r(v.w * inv);
    }
    __syncthreads();
    size_t base = ((size_t)blk * NCHUNK + kc) * 4096;
#pragma unroll
    for (int it = 0; it < 16; it++) {
        int o = t + it * 256;
        int reg = o & 3, lane = (o >> 2) & 31, m = (o >> 7) & 7, s = o >> 10;
        int rr = ((reg & 1) << 3) | (lane >> 2), kk = ((reg >> 1) << 2) | (lane & 3);
        g_featA[base + o] = tile[(m << 4) | rr][(s << 3) | kk];
    }
#pragma unroll
    for (int it = 0; it < 16; it++) {
        int o = t + it * 256;
        int slot = o & 3, lane = (o >> 2) & 31, pair = (o >> 7) & 7, s = o >> 10;
        int kk = ((slot & 1) << 2) | (lane & 3);
        int g = (pair << 1) | (slot >> 1), nl = lane >> 2;
        g_featB[base + o] = tile[(g << 3) | nl][(s << 3) | kk];
    }
}

// ---------------- coalesced fragmentize: proxy -> B blob (pad rows zero) ----
__global__ __launch_bounds__(256)
void frag_proxy_kernel()
{
    __shared__ float tile[128][33];
    int kc = blockIdx.x, blk = blockIdx.y;
    int t = threadIdx.x;
    int row = t >> 1, half = t & 1;
    int grow = blk * 128 + row;
    if (grow < CCLS) {
        float inv = g_invp[grow];
        const float* src = g_proxy + (size_t)grow * DIMK + kc * 32 + half * 16;
#pragma unroll
        for (int q = 0; q < 4; q++) {
            float4 v = *(const float4*)(src + q * 4);
            int c = half * 16 + q * 4;
            tile[row][c+0] = tf32r(v.x * inv); tile[row][c+1] = tf32r(v.y * inv);
            tile[row][c+2] = tf32r(v.z * inv); tile[row][c+3] = tf32r(v.w * inv);
        }
    } else {
#pragma unroll
        for (int q = 0; q < 4; q++) {
            int c = half * 16 + q * 4;
            tile[row][c+0] = 0.f; tile[row][c+1] = 0.f; tile[row][c+2] = 0.f; tile[row][c+3] = 0.f;
        }
    }
    __syncthreads();
    size_t base = ((size_t)blk * NCHUNK + kc) * 4096;
#pragma unroll
    for (int it = 0; it < 16; it++) {
        int o = t + it * 256;
        int slot = o & 3, lane = (o >> 2) & 31, pair = (o >> 7) & 7, s = o >> 10;
        int kk = ((slot & 1) << 2) | (lane & 3);
        int g = (pair << 1) | (slot >> 1), nl = lane >> 2;
        g_proxyB[base + o] = tile[(g << 3) | nl][(s << 3) | kk];
    }
}

// ---------------- fp32 SGEMM (small proxy projection) ----------------
__global__ __launch_bounds__(256, 2)
void sgemm_nt_kernel(const float* __restrict__ A, const float* __restrict__ B,
                     float* __restrict__ C, int M, int N, int K, int ldc)
{
    __shared__ float As[16][128];
    __shared__ float Bs[16][128];
    int tid = threadIdx.x;
    int tr = tid >> 4, tc = tid & 15;
    int row0 = blockIdx.y * 128, col0 = blockIdx.x * 128;
    int ldrow = tid >> 2, ldk = (tid & 3) * 4;
    float acc[8][8];
#pragma unroll
    for (int x = 0; x < 8; x++)
#pragma unroll
        for (int y = 0; y < 8; y++) acc[x][y] = 0.0f;
    for (int k0 = 0; k0 < K; k0 += 16) {
        __syncthreads();
#pragma unroll
        for (int h = 0; h < 2; h++) {
            int r = ldrow + 64 * h;
            float4 va = make_float4(0,0,0,0), vb = make_float4(0,0,0,0);
            if (row0 + r < M) va = *(const float4*)&A[(size_t)(row0 + r) * K + k0 + ldk];
            if (col0 + r < N) vb = *(const float4*)&B[(size_t)(col0 + r) * K + k0 + ldk];
            As[ldk+0][r]=va.x; As[ldk+1][r]=va.y; As[ldk+2][r]=va.z; As[ldk+3][r]=va.w;
            Bs[ldk+0][r]=vb.x; Bs[ldk+1][r]=vb.y; Bs[ldk+2][r]=vb.z; Bs[ldk+3][r]=vb.w;
        }
        __syncthreads();
#pragma unroll
        for (int kk = 0; kk < 16; kk++) {
            float a[8], b[8];
            *(float4*)&a[0] = *(const float4*)&As[kk][tr*8];
            *(float4*)&a[4] = *(const float4*)&As[kk][tr*8+4];
            *(float4*)&b[0] = *(const float4*)&Bs[kk][tc*8];
            *(float4*)&b[4] = *(const float4*)&Bs[kk][tc*8+4];
#pragma unroll
            for (int x = 0; x < 8; x++)
#pragma unroll
                for (int y = 0; y < 8; y++) acc[x][y] = fmaf(a[x], b[y], acc[x][y]);
        }
    }
#pragma unroll
    for (int x = 0; x < 8; x++) {
        int r = row0 + tr*8 + x;
        if (r < M)
#pragma unroll
            for (int y = 0; y < 8; y++) {
                int cc = col0 + tc*8 + y;
                if (cc < N) C[(size_t)r * ldc + cc] = acc[x][y];
            }
    }
}

// ---------------- pred = feat @ proxy^T (tf32 mma, pipelined) ----------------
#define GEMM_SMEM 98304
__global__ __launch_bounds__(256, 2)
void pred_mma_kernel()
{
    extern __shared__ char smem[];
    uint32_t sb = smem_u32(smem);
    int tid = threadIdx.x, w = tid >> 5, lane = tid & 31;
    int wr = w >> 2, wc = w & 3;
    int bi = blockIdx.y, bj = blockIdx.x;
    const float* blobA = g_featA  + (size_t)bi * NCHUNK * 4096;
    const float* blobB = g_proxyB + (size_t)bj * NCHUNK * 4096;

    float acc[4][4][4];
#pragma unroll
    for (int mt = 0; mt < 4; mt++)
#pragma unroll
        for (int nt = 0; nt < 4; nt++)
#pragma unroll
            for (int r = 0; r < 4; r++) acc[mt][nt][r] = 0.0f;

    gemm_mainloop(blobA, blobB, sb, tid, wr, wc, lane, acc);

#pragma unroll
    for (int mt = 0; mt < 4; mt++)
#pragma unroll
        for (int nt = 0; nt < 4; nt++)
#pragma unroll
            for (int rh = 0; rh < 2; rh++) {
                int row = bi*128 + wr*64 + mt*16 + (lane >> 2) + rh*8;
                int col = bj*128 + wc*32 + nt*8 + ((lane & 3) << 1);
                *(float2*)&g_pred[(size_t)row * LDPRED + col] =
                    make_float2(acc[mt][nt][rh*2], acc[mt][nt][rh*2+1]);
            }
}

// ---------------- per-row prob processing ----------------
__global__ void row_prob_kernel(const float* __restrict__ prob, const int* __restrict__ conf)
{
    __shared__ unsigned wbits[WPR];
    __shared__ float sval[256];
    __shared__ int   sidx[256];
    __shared__ float ssc[256];
    __shared__ int   scnt[256];
    int i = blockIdx.x, t = threadIdx.x;
    bool conf_i = conf[i] != 0;
    if (t < WPR) wbits[t] = 0u;
    __syncthreads();
    float best = -INFINITY; int bidx = 0x7FFFFFFF;
    float sc = 0.0f; int cnt = 0;
    for (int c = t; c < CCLS; c += 256) {
        float p = prob[(size_t)i * CCLS + c];
        if (p > best) { best = p; bidx = c; }
        if (p > 0.001f) {
            atomicOr(&wbits[c >> 5], 1u << (c & 31));
            cnt++;
            sc += p * g_pred[(size_t)i * LDPRED + c];
        }
    }
    sval[t] = best; sidx[t] = bidx; ssc[t] = sc; scnt[t] = cnt;
    __syncthreads();
    for (int s = 128; s; s >>= 1) {
        if (t < s) {
            float ov = sval[t+s]; int oi = sidx[t+s];
            if (ov > sval[t] || (ov == sval[t] && oi < sidx[t])) { sval[t] = ov; sidx[t] = oi; }
            ssc[t] += ssc[t+s]; scnt[t] += scnt[t+s];
        }
        __syncthreads();
    }
    if (t == 0) {
        int t1 = sidx[0];
        unsigned sm = 0;
#pragma unroll
        for (int w = 0; w < WPR; w++) {
            unsigned word = conf_i ? (((t1 >> 5) == w) ? (1u << (t1 & 31)) : 0u) : wbits[w];
            g_bits[(size_t)i * WPR + w] = word;
            if (word) sm |= 1u << w;
        }
        g_summ[i] = sm;
        g_pos[i] = conf_i ? g_pred[(size_t)i * LDPRED + t1] : ssc[0];
        g_candcnt[i] = conf_i ? 0 : scnt[0];
        g_notconf[i] = conf_i ? 0 : 1;
    }
}

// ---------------- fused sim: upper-triangle tiles, mask + exp ----------------
// slot ownership of g_part[s][block b rows]:
//   s >  b: tile (b, s) row-side     s == b: diagonal tile (b, b) row-side
//   s <  b: tile (s, b) col-side
__global__ __launch_bounds__(256, 2)
void fused_sim_mma_kernel()
{
    int bi = blockIdx.y, bj = blockIdx.x;
    if (bj < bi) return;

    extern __shared__ char smem[];
    uint32_t sb = smem_u32(smem);
    int tid = threadIdx.x, w = tid >> 5, lane = tid & 31;
    int wr = w >> 2, wc = w & 3;
    bool offdiag = (bj != bi);

    const float* blobA = g_featA + (size_t)bi * NCHUNK * 4096;
    const float* blobB = g_featB + (size_t)bj * NCHUNK * 4096;

    float acc[4][4][4];
#pragma unroll
    for (int mt = 0; mt < 4; mt++)
#pragma unroll
        for (int nt = 0; nt < 4; nt++)
#pragma unroll
            for (int r = 0; r < 4; r++) acc[mt][nt][r] = 0.0f;

    gemm_mainloop(blobA, blobB, sb, tid, wr, wc, lane, acc);
    __syncthreads();     // all warps done reading stage smem before overlay

    // ---- epilogue: overlay masks on stage smem
    unsigned* rbits = (unsigned*)smem;                 // [128][33]
    unsigned* cbits = rbits + 128 * 33;                // [128][33]
    unsigned* csum  = cbits + 128 * 33;                // [128]
    float*    red     = (float*)(csum + 128);          // [128][4]
    float*    colred  = red + 512;                     // [128][2]

    for (int idx = tid; idx < 128 * WPR; idx += 256) {
        rbits[(idx >> 5) * 33 + (idx & 31)] = g_bits[(size_t)(bi*128) * WPR + idx];
        cbits[(idx >> 5) * 33 + (idx & 31)] = g_bits[(size_t)(bj*128) * WPR + idx];
    }
    if (tid < 128) csum[tid] = g_summ[bj*128 + tid];
    __syncthreads();

    float rowacc[4][2], colacc[4][2];
    unsigned rsum[4][2];
#pragma unroll
    for (int mt = 0; mt < 4; mt++)
#pragma unroll
        for (int rh = 0; rh < 2; rh++) {
            rowacc[mt][rh] = 0.0f;
            rsum[mt][rh] = g_summ[bi*128 + wr*64 + mt*16 + (lane >> 2) + rh*8];
        }
#pragma unroll
    for (int nt = 0; nt < 4; nt++)
#pragma unroll
        for (int cb = 0; cb < 2; cb++) colacc[nt][cb] = 0.0f;

#pragma unroll
    for (int mt = 0; mt < 4; mt++)
#pragma unroll
        for (int nt = 0; nt < 4; nt++)
#pragma unroll
            for (int r = 0; r < 4; r++) {
                int rh = r >> 1, cb = r & 1;
                float v = acc[mt][nt][r];
                if (v >= 1e-6f) {
                    int row_l = wr*64 + mt*16 + (lane >> 2) + rh*8;
                    int col_l = wc*32 + nt*8 + ((lane & 3) << 1) + cb;
                    unsigned hit = rsum[mt][rh] & csum[col_l];
                    bool masked = false;
                    while (hit) {
                        int wd = __ffs((int)hit) - 1;
                        if (rbits[row_l*33 + wd] & cbits[col_l*33 + wd]) { masked = true; break; }
                        hit &= hit - 1;
                    }
                    if (!masked) {
                        float e = __expf(v);
                        rowacc[mt][rh] += e;
                        colacc[nt][cb] += e;
                    }
                }
            }

    // row reduce (quad lanes, then 4 wc warps)
#pragma unroll
    for (int mt = 0; mt < 4; mt++)
#pragma unroll
        for (int rh = 0; rh < 2; rh++) {
            float v = rowacc[mt][rh];
            v += __shfl_xor_sync(0xFFFFFFFFu, v, 1);
            v += __shfl_xor_sync(0xFFFFFFFFu, v, 2);
            if ((lane & 3) == 0)
                red[(wr*64 + mt*16 + (lane >> 2) + rh*8) * 4 + wc] = v;
        }
    // col reduce (octet lanes, then 2 wr warps)
#pragma unroll
    for (int nt = 0; nt < 4; nt++)
#pragma unroll
        for (int cb = 0; cb < 2; cb++) {
            float v = colacc[nt][cb];
            v += __shfl_xor_sync(0xFFFFFFFFu, v, 4);
            v += __shfl_xor_sync(0xFFFFFFFFu, v, 8);
            v += __shfl_xor_sync(0xFFFFFFFFu, v, 16);
            if ((lane >> 2) == 0)
                colred[(wc*32 + nt*8 + ((lane & 3) << 1) + cb) * 2 + wr] = v;
        }
    __syncthreads();
    if (tid < 128) {
        float s = red[tid*4] + red[tid*4+1] + red[tid*4+2] + red[tid*4+3];
        g_part[(size_t)bj * NROWS + bi*128 + tid] = s;          // slot bj, rows of block bi
        if (offdiag)
            g_part[(size_t)bi * NROWS + bj*128 + tid] =          // slot bi, rows of block bj
                colred[tid*2] + colred[tid*2+1];
    }
}

// ---------------- loss reduction stage A (parallel, coalesced) ---------------
__global__ void loss_partial_kernel()
{
    __shared__ float sl[256];
    __shared__ int   sc[256];
    __shared__ int   sn[256];
    int t = threadIdx.x;
    int i = blockIdx.x * 256 + t;
    float pos = g_pos[i];
    float S = expf(pos);
#pragma unroll 8
    for (int s = 0; s < NBLK; s++) S += g_part[(size_t)s * NROWS + i];
    sl[t] = logf(S) - pos;
    sc[t] = g_candcnt[i];
    sn[t] = g_notconf[i];
    __syncthreads();
    for (int s = 128; s; s >>= 1) {
        if (t < s) { sl[t] += sl[t+s]; sc[t] += sc[t+s]; sn[t] += sn[t+s]; }
        __syncthreads();
    }
    if (t == 0) { g_redl[blockIdx.x] = sl[0]; g_redc[blockIdx.x] = sc[0]; g_redn[blockIdx.x] = sn[0]; }
}

// ---------------- loss reduction stage B ----------------
__global__ void final_kernel(float* __restrict__ out)
{
    int t = threadIdx.x;        // 32 threads
    float l = g_redl[t];
    int   c = g_redc[t];
    int   n = g_redn[t];
#pragma unroll
    for (int o = 16; o; o >>= 1) {
        l += __shfl_xor_sync(0xFFFFFFFFu, l, o);
        c += __shfl_xor_sync(0xFFFFFFFFu, c, o);
        n += __shfl_xor_sync(0xFFFFFFFFu, n, o);
    }
    if (t == 0) {
        out[0] = l / (float)NROWS;
        out[1] = (n > 0) ? ((float)c / (float)n) : 0.0f;
    }
}

// ---------------- launch ----------------
extern "C" void kernel_launch(void* const* d_in, const int* in_sizes, int n_in,
                              void* d_out, int out_size)
{
    const float* feature   = (const float*)d_in[0];
    const float* proxy_raw = (const float*)d_in[1];
    const float* cPw       = (const float*)d_in[2];
    const float* prob      = (const float*)d_in[3];
    const int*   conf      = (const int*)d_in[4];
    float* out = (float*)d_out;

    void *p_proxy, *p_inv, *p_invp;
    cudaGetSymbolAddress(&p_proxy, g_proxy);
    cudaGetSymbolAddress(&p_inv, g_inv);
    cudaGetSymbolAddress(&p_invp, g_invp);

    cudaFuncSetAttribute(pred_mma_kernel, cudaFuncAttributeMaxDynamicSharedMemorySize, GEMM_SMEM);
    cudaFuncSetAttribute(fused_sim_mma_kernel, cudaFuncAttributeMaxDynamicSharedMemorySize, GEMM_SMEM);

    // 1) proxy = proxy_raw @ cP_weight^T (fp32)
    sgemm_nt_kernel<<<dim3(4, 8), 256>>>(proxy_raw, cPw, (float*)p_proxy, CCLS, DIMK, DIMK, DIMK);
    // 2) inverse norms
    inv_norm_kernel<<<NROWS / 8, 256>>>(feature, (float*)p_inv, NROWS);
    inv_norm_kernel<<<(CCLS + 7) / 8, 256>>>((const float*)p_proxy, (float*)p_invp, CCLS);
    // 3) coalesced fragmentize
    frag_feat_kernel<<<dim3(NCHUNK, NBLK), 256>>>(feature);
    frag_proxy_kernel<<<dim3(NCHUNK, NPAD / 128), 256>>>();
    // 4) pred = feat @ proxy^T
    pred_mma_kernel<<<dim3(NPAD / 128, NROWS / 128), 256, GEMM_SMEM>>>();
    // 5) per-row prob/bits/pos
    row_prob_kernel<<<NROWS, 256>>>(prob, conf);
    // 6) fused sim (upper triangle) + mask + exp partials
    fused_sim_mma_kernel<<<dim3(NBLK, NBLK), 256, GEMM_SMEM>>>();
    // 7) loss + sc_num
    loss_partial_kernel<<<NROWS / 256, 256>>>();
    final_kernel<<<1, 32>>>(out);
}

// round 6
// speedup vs baseline: 3.8794x; 1.0320x over previous
#include <cuda_runtime.h>
#include <math.h>
#include <stdint.h>

// ---------------- problem constants ----------------
#define NROWS  8192
#define DIMK   512
#define CCLS   1000
#define LDPRED 1024
#define WPR    32
#define NPAD   1024
#define NBLK   64            // NROWS / 128
#define NCHUNK 16            // DIMK / 32

// ---------------- device scratch (static) ----------------
__device__ float    g_featA[NROWS * DIMK];       // A-fragment-ordered feat (16 chunks x 16KB / blk)
__device__ float    g_featB[NROWS * DIMK];       // B-fragment-ordered feat
__device__ float    g_proxy[NPAD * DIMK];        // projected proxies (natural layout)
__device__ float    g_proxyB[NPAD * DIMK];       // B-fragment-ordered proxies
__device__ float    g_pred[NROWS * LDPRED];      // feat @ proxy^T
__device__ float    g_inv[NROWS];
__device__ float    g_invp[NPAD];
__device__ unsigned g_bits[NROWS * WPR];         // packed candidate bits (1024 bits/row)
__device__ unsigned g_bitsA[NROWS * 256];        // s8 A-fragment blobs (8 chunks x 16KB / blk)
__device__ unsigned g_bitsB[NROWS * 256];        // s8 B-fragment blobs
__device__ float    g_pos[NROWS];
__device__ int      g_candcnt[NROWS];
__device__ int      g_notconf[NROWS];
__device__ float    g_part[NBLK * NROWS];        // merged exp-sum partials (disjoint slots)
__device__ float    g_redl[32];
__device__ int      g_redc[32];
__device__ int      g_redn[32];

// ---------------- small helpers ----------------
__device__ __forceinline__ uint32_t smem_u32(const void* p) {
    uint32_t a;
    asm("{ .reg .u64 t; cvta.to.shared.u64 t, %1; cvt.u32.u64 %0, t; }" : "=r"(a) : "l"(p));
    return a;
}
__device__ __forceinline__ float4 lds128(uint32_t a) {
    float4 r;
    asm volatile("ld.shared.v4.f32 {%0,%1,%2,%3}, [%4];"
                 : "=f"(r.x), "=f"(r.y), "=f"(r.z), "=f"(r.w) : "r"(a));
    return r;
}
__device__ __forceinline__ float tf32r(float x) {
    uint32_t u;
    asm("cvt.rna.tf32.f32 %0, %1;" : "=r"(u) : "f"(x));
    return __uint_as_float(u);
}
__device__ __forceinline__ void cp16(uint32_t dst, const void* src) {
    asm volatile("cp.async.cg.shared.global [%0], [%1], 16;" :: "r"(dst), "l"(src));
}
__device__ __forceinline__ void cp_commit() { asm volatile("cp.async.commit_group;"); }
template <int N> __device__ __forceinline__ void cp_wait() {
    asm volatile("cp.async.wait_group %0;" :: "n"(N) : "memory");
}
__device__ __forceinline__ void mma_tf32(float c[4], const uint32_t a[4], const uint32_t b[2]) {
    asm volatile(
        "mma.sync.aligned.m16n8k8.row.col.f32.tf32.tf32.f32 "
        "{%0,%1,%2,%3}, {%4,%5,%6,%7}, {%8,%9}, {%0,%1,%2,%3};"
        : "+f"(c[0]), "+f"(c[1]), "+f"(c[2]), "+f"(c[3])
        : "r"(a[0]), "r"(a[1]), "r"(a[2]), "r"(a[3]), "r"(b[0]), "r"(b[1]));
}
__device__ __forceinline__ void mma_s8(int c[4], const uint32_t a[4], const uint32_t b[2]) {
    asm volatile(
        "mma.sync.aligned.m16n8k32.row.col.s32.s8.s8.s32 "
        "{%0,%1,%2,%3}, {%4,%5,%6,%7}, {%8,%9}, {%0,%1,%2,%3};"
        : "+r"(c[0]), "+r"(c[1]), "+r"(c[2]), "+r"(c[3])
        : "r"(a[0]), "r"(a[1]), "r"(a[2]), "r"(a[3]), "r"(b[0]), "r"(b[1]));
}

// ---------------- shared GEMM core ----------------
// uniform stage: A 16KB @ +0, B 16KB @ +16384; 3 stages x 32KB.
__device__ __forceinline__ void ldg_stage(uint32_t st, const char* a, const char* b, int tid)
{
#pragma unroll
    for (int ii = 0; ii < 4; ii++) {
        int o = (tid + (ii << 8)) << 4;
        cp16(st + o, a + o);
        cp16(st + 16384 + o, b + o);
    }
    cp_commit();
}

__device__ __forceinline__ void compute_chunk_f(uint32_t Ab, uint32_t Bb,
                                                float (&acc)[4][4][4], int wr, int wc, int lane)
{
#pragma unroll
    for (int s = 0; s < 4; s++) {
        uint32_t a[4][4];
#pragma unroll
        for (int mt = 0; mt < 4; mt++) {
            float4 av = lds128(Ab + (((((s << 3) | (wr * 4 + mt)) << 5) | lane) << 4));
            a[mt][0] = __float_as_uint(av.x); a[mt][1] = __float_as_uint(av.y);
            a[mt][2] = __float_as_uint(av.z); a[mt][3] = __float_as_uint(av.w);
        }
        uint32_t b[4][2];
#pragma unroll
        for (int pl = 0; pl < 2; pl++) {
            float4 bv = lds128(Bb + (((((s << 3) | (wc * 2 + pl)) << 5) | lane) << 4));
            b[2*pl][0]   = __float_as_uint(bv.x); b[2*pl][1]   = __float_as_uint(bv.y);
            b[2*pl+1][0] = __float_as_uint(bv.z); b[2*pl+1][1] = __float_as_uint(bv.w);
        }
#pragma unroll
        for (int mt = 0; mt < 4; mt++)
#pragma unroll
            for (int nt = 0; nt < 4; nt++)
                mma_tf32(acc[mt][nt], a[mt], b[nt]);
    }
}

__device__ __forceinline__ void compute_chunk_i(uint32_t Ab, uint32_t Bb,
                                                int (&acc)[4][4][4], int wr, int wc, int lane)
{
#pragma unroll
    for (int s = 0; s < 4; s++) {
        uint32_t a[4][4];
#pragma unroll
        for (int mt = 0; mt < 4; mt++) {
            float4 av = lds128(Ab + (((((s << 3) | (wr * 4 + mt)) << 5) | lane) << 4));
            a[mt][0] = __float_as_uint(av.x); a[mt][1] = __float_as_uint(av.y);
            a[mt][2] = __float_as_uint(av.z); a[mt][3] = __float_as_uint(av.w);
        }
        uint32_t b[4][2];
#pragma unroll
        for (int pl = 0; pl < 2; pl++) {
            float4 bv = lds128(Bb + (((((s << 3) | (wc * 2 + pl)) << 5) | lane) << 4));
            b[2*pl][0]   = __float_as_uint(bv.x); b[2*pl][1]   = __float_as_uint(bv.y);
            b[2*pl+1][0] = __float_as_uint(bv.z); b[2*pl+1][1] = __float_as_uint(bv.w);
        }
#pragma unroll
        for (int mt = 0; mt < 4; mt++)
#pragma unroll
            for (int nt = 0; nt < 4; nt++)
                mma_s8(acc[mt][nt], a[mt], b[nt]);
    }
}

// ---------------- inverse L2 norms (one warp per row) ----------------
__global__ void inv_norm_kernel(const float* __restrict__ in, float* __restrict__ outinv,
                                int nrows)
{
    int row = blockIdx.x * 8 + (threadIdx.x >> 5);
    int lane = threadIdx.x & 31;
    if (row >= nrows) return;
    const float4* p = (const float4*)(in + (size_t)row * DIMK);
    float ss = 0.0f;
#pragma unroll
    for (int q = 0; q < 4; q++) {
        float4 v = p[lane + 32 * q];
        ss += v.x*v.x + v.y*v.y + v.z*v.z + v.w*v.w;
    }
#pragma unroll
    for (int o = 16; o; o >>= 1) ss += __shfl_xor_sync(0xFFFFFFFFu, ss, o);
    if (lane == 0) outinv[row] = 1.0f / fmaxf(sqrtf(ss), 1e-12f);
}

// ---------------- coalesced fragmentize: feat -> A & B blobs ----------------
__global__ __launch_bounds__(256)
void frag_feat_kernel(const float* __restrict__ in)
{
    __shared__ float tile[128][33];
    int kc = blockIdx.x, blk = blockIdx.y;
    int t = threadIdx.x;
    int row = t >> 1, half = t & 1;
    float inv = g_inv[blk * 128 + row];
    const float* src = in + (size_t)(blk * 128 + row) * DIMK + kc * 32 + half * 16;
#pragma unroll
    for (int q = 0; q < 4; q++) {
        float4 v = *(const float4*)(src + q * 4);
        int c = half * 16 + q * 4;
        tile[row][c+0] = tf32r(v.x * inv); tile[row][c+1] = tf32r(v.y * inv);
        tile[row][c+2] = tf32r(v.z * inv); tile[row][c+3] = tf32r(v.w * inv);
    }
    __syncthreads();
    size_t base = ((size_t)blk * NCHUNK + kc) * 4096;
#pragma unroll
    for (int it = 0; it < 16; it++) {
        int o = t + it * 256;
        int reg = o & 3, lane = (o >> 2) & 31, m = (o >> 7) & 7, s = o >> 10;
        int rr = ((reg & 1) << 3) | (lane >> 2), kk = ((reg >> 1) << 2) | (lane & 3);
        g_featA[base + o] = tile[(m << 4) | rr][(s << 3) | kk];
    }
#pragma unroll
    for (int it = 0; it < 16; it++) {
        int o = t + it * 256;
        int slot = o & 3, lane = (o >> 2) & 31, pair = (o >> 7) & 7, s = o >> 10;
        int kk = ((slot & 1) << 2) | (lane & 3);
        int g = (pair << 1) | (slot >> 1), nl = lane >> 2;
        g_featB[base + o] = tile[(g << 3) | nl][(s << 3) | kk];
    }
}

// ---------------- coalesced fragmentize: proxy -> B blob (pad rows zero) ----
__global__ __launch_bounds__(256)
void frag_proxy_kernel()
{
    __shared__ float tile[128][33];
    int kc = blockIdx.x, blk = blockIdx.y;
    int t = threadIdx.x;
    int row = t >> 1, half = t & 1;
    int grow = blk * 128 + row;
    if (grow < CCLS) {
        float inv = g_invp[grow];
        const float* src = g_proxy + (size_t)grow * DIMK + kc * 32 + half * 16;
#pragma unroll
        for (int q = 0; q < 4; q++) {
            float4 v = *(const float4*)(src + q * 4);
            int c = half * 16 + q * 4;
            tile[row][c+0] = tf32r(v.x * inv); tile[row][c+1] = tf32r(v.y * inv);
            tile[row][c+2] = tf32r(v.z * inv); tile[row][c+3] = tf32r(v.w * inv);
        }
    } else {
#pragma unroll
        for (int q = 0; q < 4; q++) {
            int c = half * 16 + q * 4;
            tile[row][c+0] = 0.f; tile[row][c+1] = 0.f; tile[row][c+2] = 0.f; tile[row][c+3] = 0.f;
        }
    }
    __syncthreads();
    size_t base = ((size_t)blk * NCHUNK + kc) * 4096;
#pragma unroll
    for (int it = 0; it < 16; it++) {
        int o = t + it * 256;
        int slot = o & 3, lane = (o >> 2) & 31, pair = (o >> 7) & 7, s = o >> 10;
        int kk = ((slot & 1) << 2) | (lane & 3);
        int g = (pair << 1) | (slot >> 1), nl = lane >> 2;
        g_proxyB[base + o] = tile[(g << 3) | nl][(s << 3) | kk];
    }
}

// ---------------- expand candidate bits -> s8 fragment blobs ----------------
__global__ __launch_bounds__(256)
void frag_bits_kernel()
{
    int chunk = blockIdx.x;       // 0..7 (128 classes each; classes >=1000 are zero bits)
    int blk   = blockIdx.y;       // 0..63
    int t = threadIdx.x;
    size_t base = ((size_t)blk * 8 + chunk) * 4096;   // u32 index
#pragma unroll
    for (int it = 0; it < 16; it++) {
        int o4 = t + it * 256;
        int reg  = o4 & 3;
        int lane = (o4 >> 2) & 31;
        int m    = (o4 >> 7) & 7;
        int s    = o4 >> 10;
        // A-side
        int rr  = ((reg & 1) << 3) | (lane >> 2);
        int row = blk * 128 + (m << 4) + rr;
        int c0  = chunk * 128 + s * 32 + (((reg >> 1) << 4) | ((lane & 3) << 2));
        unsigned w = g_bits[(size_t)row * WPR + (c0 >> 5)];
        unsigned nib = (w >> (c0 & 31)) & 0xFu;
        g_bitsA[base + o4] = (nib & 1u) | ((nib & 2u) << 7) | ((nib & 4u) << 14) | ((nib & 8u) << 21);
        // B-side
        int g   = (m << 1) | (reg >> 1);
        int col = blk * 128 + (g << 3) + (lane >> 2);
        int c0b = chunk * 128 + s * 32 + (((reg & 1) << 4) | ((lane & 3) << 2));
        unsigned wb = g_bits[(size_t)col * WPR + (c0b >> 5)];
        unsigned nb = (wb >> (c0b & 31)) & 0xFu;
        g_bitsB[base + o4] = (nb & 1u) | ((nb & 2u) << 7) | ((nb & 4u) << 14) | ((nb & 8u) << 21);
    }
}

// ---------------- fp32 SGEMM (small proxy projection) ----------------
__global__ __launch_bounds__(256, 2)
void sgemm_nt_kernel(const float* __restrict__ A, const float* __restrict__ B,
                     float* __restrict__ C, int M, int N, int K, int ldc)
{
    __shared__ float As[16][128];
    __shared__ float Bs[16][128];
    int tid = threadIdx.x;
    int tr = tid >> 4, tc = tid & 15;
    int row0 = blockIdx.y * 128, col0 = blockIdx.x * 128;
    int ldrow = tid >> 2, ldk = (tid & 3) * 4;
    float acc[8][8];
#pragma unroll
    for (int x = 0; x < 8; x++)
#pragma unroll
        for (int y = 0; y < 8; y++) acc[x][y] = 0.0f;
    for (int k0 = 0; k0 < K; k0 += 16) {
        __syncthreads();
#pragma unroll
        for (int h = 0; h < 2; h++) {
            int r = ldrow + 64 * h;
            float4 va = make_float4(0,0,0,0), vb = make_float4(0,0,0,0);
            if (row0 + r < M) va = *(const float4*)&A[(size_t)(row0 + r) * K + k0 + ldk];
            if (col0 + r < N) vb = *(const float4*)&B[(size_t)(col0 + r) * K + k0 + ldk];
            As[ldk+0][r]=va.x; As[ldk+1][r]=va.y; As[ldk+2][r]=va.z; As[ldk+3][r]=va.w;
            Bs[ldk+0][r]=vb.x; Bs[ldk+1][r]=vb.y; Bs[ldk+2][r]=vb.z; Bs[ldk+3][r]=vb.w;
        }
        __syncthreads();
#pragma unroll
        for (int kk = 0; kk < 16; kk++) {
            float a[8], b[8];
            *(float4*)&a[0] = *(const float4*)&As[kk][tr*8];
            *(float4*)&a[4] = *(const float4*)&As[kk][tr*8+4];
            *(float4*)&b[0] = *(const float4*)&Bs[kk][tc*8];
            *(float4*)&b[4] = *(const float4*)&Bs[kk][tc*8+4];
#pragma unroll
            for (int x = 0; x < 8; x++)
#pragma unroll
                for (int y = 0; y < 8; y++) acc[x][y] = fmaf(a[x], b[y], acc[x][y]);
        }
    }
#pragma unroll
    for (int x = 0; x < 8; x++) {
        int r = row0 + tr*8 + x;
        if (r < M)
#pragma unroll
            for (int y = 0; y < 8; y++) {
                int cc = col0 + tc*8 + y;
                if (cc < N) C[(size_t)r * ldc + cc] = acc[x][y];
            }
    }
}

// ---------------- pred = feat @ proxy^T (tf32 mma, pipelined) ----------------
#define GEMM_SMEM 98304
__global__ __launch_bounds__(256, 2)
void pred_mma_kernel()
{
    extern __shared__ char smem[];
    uint32_t sb = smem_u32(smem);
    int tid = threadIdx.x, w = tid >> 5, lane = tid & 31;
    int wr = w >> 2, wc = w & 3;
    int bi = blockIdx.y, bj = blockIdx.x;
    const char* Abase = (const char*)g_featA  + (size_t)bi * NCHUNK * 16384;
    const char* Bbase = (const char*)g_proxyB + (size_t)bj * NCHUNK * 16384;

    float acc[4][4][4];
#pragma unroll
    for (int mt = 0; mt < 4; mt++)
#pragma unroll
        for (int nt = 0; nt < 4; nt++)
#pragma unroll
            for (int r = 0; r < 4; r++) acc[mt][nt][r] = 0.0f;

    ldg_stage(sb,         Abase,         Bbase,         tid);
    ldg_stage(sb + 32768, Abase + 16384, Bbase + 16384, tid);
#pragma unroll 1
    for (int k = 0; k < NCHUNK; k++) {
        if (k < NCHUNK - 1) cp_wait<1>(); else cp_wait<0>();
        __syncthreads();
        if (k + 2 < NCHUNK)
            ldg_stage(sb + (uint32_t)((k + 2) % 3) * 32768u,
                      Abase + (size_t)(k + 2) * 16384, Bbase + (size_t)(k + 2) * 16384, tid);
        uint32_t st = sb + (uint32_t)(k % 3) * 32768u;
        compute_chunk_f(st, st + 16384, acc, wr, wc, lane);
    }

#pragma unroll
    for (int mt = 0; mt < 4; mt++)
#pragma unroll
        for (int nt = 0; nt < 4; nt++)
#pragma unroll
            for (int rh = 0; rh < 2; rh++) {
                int row = bi*128 + wr*64 + mt*16 + (lane >> 2) + rh*8;
                int col = bj*128 + wc*32 + nt*8 + ((lane & 3) << 1);
                *(float2*)&g_pred[(size_t)row * LDPRED + col] =
                    make_float2(acc[mt][nt][rh*2], acc[mt][nt][rh*2+1]);
            }
}

// ---------------- per-row prob processing ----------------
__global__ void row_prob_kernel(const float* __restrict__ prob, const int* __restrict__ conf)
{
    __shared__ unsigned wbits[WPR];
    __shared__ float sval[256];
    __shared__ int   sidx[256];
    __shared__ float ssc[256];
    __shared__ int   scnt[256];
    int i = blockIdx.x, t = threadIdx.x;
    bool conf_i = conf[i] != 0;
    if (t < WPR) wbits[t] = 0u;
    __syncthreads();
    float best = -INFINITY; int bidx = 0x7FFFFFFF;
    float sc = 0.0f; int cnt = 0;
    for (int c = t; c < CCLS; c += 256) {
        float p = prob[(size_t)i * CCLS + c];
        if (p > best) { best = p; bidx = c; }
        if (p > 0.001f) {
            atomicOr(&wbits[c >> 5], 1u << (c & 31));
            cnt++;
            sc += p * g_pred[(size_t)i * LDPRED + c];
        }
    }
    sval[t] = best; sidx[t] = bidx; ssc[t] = sc; scnt[t] = cnt;
    __syncthreads();
    for (int s = 128; s; s >>= 1) {
        if (t < s) {
            float ov = sval[t+s]; int oi = sidx[t+s];
            if (ov > sval[t] || (ov == sval[t] && oi < sidx[t])) { sval[t] = ov; sidx[t] = oi; }
            ssc[t] += ssc[t+s]; scnt[t] += scnt[t+s];
        }
        __syncthreads();
    }
    if (t == 0) {
        int t1 = sidx[0];
#pragma unroll
        for (int w = 0; w < WPR; w++) {
            unsigned word = conf_i ? (((t1 >> 5) == w) ? (1u << (t1 & 31)) : 0u) : wbits[w];
            g_bits[(size_t)i * WPR + w] = word;
        }
        g_pos[i] = conf_i ? g_pred[(size_t)i * LDPRED + t1] : ssc[0];
        g_candcnt[i] = conf_i ? 0 : scnt[0];
        g_notconf[i] = conf_i ? 0 : 1;
    }
}

// ---------------- fused sim: two-pass (s8 mask GEMM + tf32 sim GEMM) ---------
// g_part slot ownership: s>b: tile(b,s) rows; s==b: diag rows; s<b: tile(s,b) cols
__device__ __forceinline__ void chunk_src(int k, int bi, int bj,
                                          const char*& a, const char*& b)
{
    if (k < 8) {
        a = (const char*)g_bitsA + (((size_t)bi * 8 + k) << 14);
        b = (const char*)g_bitsB + (((size_t)bj * 8 + k) << 14);
    } else {
        a = (const char*)g_featA + (((size_t)bi * 16 + (k - 8)) << 14);
        b = (const char*)g_featB + (((size_t)bj * 16 + (k - 8)) << 14);
    }
}

__global__ __launch_bounds__(256, 2)
void fused_sim_mma_kernel()
{
    int bi = blockIdx.y, bj = blockIdx.x;
    if (bj < bi) return;

    extern __shared__ char smem[];
    uint32_t sb = smem_u32(smem);
    int tid = threadIdx.x, w = tid >> 5, lane = tid & 31;
    int wr = w >> 2, wc = w & 3;
    bool offdiag = (bj != bi);

    union Acc { int i[4][4][4]; float f[4][4][4]; } acc;
#pragma unroll
    for (int mt = 0; mt < 4; mt++)
#pragma unroll
        for (int nt = 0; nt < 4; nt++)
#pragma unroll
            for (int r = 0; r < 4; r++) acc.i[mt][nt][r] = 0;

    uint32_t keep0 = 0, keep1 = 0;

    {
        const char *a, *b;
        chunk_src(0, bi, bj, a, b); ldg_stage(sb,         a, b, tid);
        chunk_src(1, bi, bj, a, b); ldg_stage(sb + 32768, a, b, tid);
    }
#pragma unroll 1
    for (int k = 0; k < 24; k++) {
        if (k < 23) cp_wait<1>(); else cp_wait<0>();
        __syncthreads();
        if (k + 2 < 24) {
            const char *a, *b;
            chunk_src(k + 2, bi, bj, a, b);
            ldg_stage(sb + (uint32_t)((k + 2) % 3) * 32768u, a, b, tid);
        }
        uint32_t st = sb + (uint32_t)(k % 3) * 32768u;
        if (k < 8) compute_chunk_i(st, st + 16384, acc.i, wr, wc, lane);
        else       compute_chunk_f(st, st + 16384, acc.f, wr, wc, lane);
        if (k == 7) {
            // compress intersection counts -> keep bits, then zero fp accumulators
#pragma unroll
            for (int mt = 0; mt < 4; mt++)
#pragma unroll
                for (int nt = 0; nt < 4; nt++)
#pragma unroll
                    for (int r = 0; r < 4; r++) {
                        int idx = mt*16 + nt*4 + r;
                        unsigned bit = (acc.i[mt][nt][r] == 0) ? 1u : 0u;
                        if (idx < 32) keep0 |= bit << idx;
                        else          keep1 |= bit << (idx - 32);
                        acc.f[mt][nt][r] = 0.0f;
                    }
        }
    }
    __syncthreads();     // all warps done with stage smem before overlay

    float* red    = (float*)smem;          // [128][4]
    float* colred = red + 512;             // [128][2]

    float rowacc[4][2], colacc[4][2];
#pragma unroll
    for (int mt = 0; mt < 4; mt++)
#pragma unroll
        for (int rh = 0; rh < 2; rh++) rowacc[mt][rh] = 0.0f;
#pragma unroll
    for (int nt = 0; nt < 4; nt++)
#pragma unroll
        for (int cb = 0; cb < 2; cb++) colacc[nt][cb] = 0.0f;

#pragma unroll
    for (int mt = 0; mt < 4; mt++)
#pragma unroll
        for (int nt = 0; nt < 4; nt++)
#pragma unroll
            for (int r = 0; r < 4; r++) {
                int idx = mt*16 + nt*4 + r;
                unsigned kp = (idx < 32) ? (keep0 >> idx) : (keep1 >> (idx - 32));
                float v = acc.f[mt][nt][r];
                if ((kp & 1u) && v >= 1e-6f) {
                    float e = __expf(v);
                    rowacc[mt][r >> 1] += e;
                    colacc[nt][r & 1]  += e;
                }
            }

    // row reduce (quad lanes, then 4 wc warps)
#pragma unroll
    for (int mt = 0; mt < 4; mt++)
#pragma unroll
        for (int rh = 0; rh < 2; rh++) {
            float v = rowacc[mt][rh];
            v += __shfl_xor_sync(0xFFFFFFFFu, v, 1);
            v += __shfl_xor_sync(0xFFFFFFFFu, v, 2);
            if ((lane & 3) == 0)
                red[(wr*64 + mt*16 + (lane >> 2) + rh*8) * 4 + wc] = v;
        }
    // col reduce (octet lanes, then 2 wr warps)
#pragma unroll
    for (int nt = 0; nt < 4; nt++)
#pragma unroll
        for (int cb = 0; cb < 2; cb++) {
            float v = colacc[nt][cb];
            v += __shfl_xor_sync(0xFFFFFFFFu, v, 4);
            v += __shfl_xor_sync(0xFFFFFFFFu, v, 8);
            v += __shfl_xor_sync(0xFFFFFFFFu, v, 16);
            if ((lane >> 2) == 0)
                colred[(wc*32 + nt*8 + ((lane & 3) << 1) + cb) * 2 + wr] = v;
        }
    __syncthreads();
    if (tid < 128) {
        float s = red[tid*4] + red[tid*4+1] + red[tid*4+2] + red[tid*4+3];
        g_part[(size_t)bj * NROWS + bi*128 + tid] = s;
        if (offdiag)
            g_part[(size_t)bi * NROWS + bj*128 + tid] = colred[tid*2] + colred[tid*2+1];
    }
}

// ---------------- loss reduction stage A (parallel, coalesced) ---------------
__global__ void loss_partial_kernel()
{
    __shared__ float sl[256];
    __shared__ int   sc[256];
    __shared__ int   sn[256];
    int t = threadIdx.x;
    int i = blockIdx.x * 256 + t;
    float pos = g_pos[i];
    float S = expf(pos);
#pragma unroll 8
    for (int s = 0; s < NBLK; s++) S += g_part[(size_t)s * NROWS + i];
    sl[t] = logf(S) - pos;
    sc[t] = g_candcnt[i];
    sn[t] = g_notconf[i];
    __syncthreads();
    for (int s = 128; s; s >>= 1) {
        if (t < s) { sl[t] += sl[t+s]; sc[t] += sc[t+s]; sn[t] += sn[t+s]; }
        __syncthreads();
    }
    if (t == 0) { g_redl[blockIdx.x] = sl[0]; g_redc[blockIdx.x] = sc[0]; g_redn[blockIdx.x] = sn[0]; }
}

// ---------------- loss reduction stage B ----------------
__global__ void final_kernel(float* __restrict__ out)
{
    int t = threadIdx.x;        // 32 threads
    float l = g_redl[t];
    int   c = g_redc[t];
    int   n = g_redn[t];
#pragma unroll
    for (int o = 16; o; o >>= 1) {
        l += __shfl_xor_sync(0xFFFFFFFFu, l, o);
        c += __shfl_xor_sync(0xFFFFFFFFu, c, o);
        n += __shfl_xor_sync(0xFFFFFFFFu, n, o);
    }
    if (t == 0) {
        out[0] = l / (float)NROWS;
        out[1] = (n > 0) ? ((float)c / (float)n) : 0.0f;
    }
}

// ---------------- launch ----------------
extern "C" void kernel_launch(void* const* d_in, const int* in_sizes, int n_in,
                              void* d_out, int out_size)
{
    const float* feature   = (const float*)d_in[0];
    const float* proxy_raw = (const float*)d_in[1];
    const float* cPw       = (const float*)d_in[2];
    const float* prob      = (const float*)d_in[3];
    const int*   conf      = (const int*)d_in[4];
    float* out = (float*)d_out;

    void *p_proxy, *p_inv, *p_invp;
    cudaGetSymbolAddress(&p_proxy, g_proxy);
    cudaGetSymbolAddress(&p_inv, g_inv);
    cudaGetSymbolAddress(&p_invp, g_invp);

    cudaFuncSetAttribute(pred_mma_kernel, cudaFuncAttributeMaxDynamicSharedMemorySize, GEMM_SMEM);
    cudaFuncSetAttribute(fused_sim_mma_kernel, cudaFuncAttributeMaxDynamicSharedMemorySize, GEMM_SMEM);

    // 1) proxy = proxy_raw @ cP_weight^T (fp32)
    sgemm_nt_kernel<<<dim3(4, 8), 256>>>(proxy_raw, cPw, (float*)p_proxy, CCLS, DIMK, DIMK, DIMK);
    // 2) inverse norms
    inv_norm_kernel<<<NROWS / 8, 256>>>(feature, (float*)p_inv, NROWS);
    inv_norm_kernel<<<(CCLS + 7) / 8, 256>>>((const float*)p_proxy, (float*)p_invp, CCLS);
    // 3) coalesced fragmentize
    frag_feat_kernel<<<dim3(NCHUNK, NBLK), 256>>>(feature);
    frag_proxy_kernel<<<dim3(NCHUNK, NPAD / 128), 256>>>();
    // 4) pred = feat @ proxy^T
    pred_mma_kernel<<<dim3(NPAD / 128, NROWS / 128), 256, GEMM_SMEM>>>();
    // 5) per-row prob/bits/pos
    row_prob_kernel<<<NROWS, 256>>>(prob, conf);
    // 6) expand candidate bits to s8 fragment blobs
    frag_bits_kernel<<<dim3(8, NBLK), 256>>>();
    // 7) fused sim (upper triangle): s8 mask GEMM + tf32 sim GEMM + exp partials
    fused_sim_mma_kernel<<<dim3(NBLK, NBLK), 256, GEMM_SMEM>>>();
    // 8) loss + sc_num
    loss_partial_kernel<<<NROWS / 256, 256>>>();
    final_kernel<<<1, 32>>>(out);
}